// round 15
// baseline (speedup 1.0000x reference)
#include <cuda_runtime.h>
#include <math.h>
#include <float.h>

#define BB 2
#define NN 8192
#define KK 16
#define CC 64
#define BN (BB*NN)

typedef unsigned long long ull;

__device__ __forceinline__ ull pk(float a, float b) {
    ull d; asm("mov.b64 %0,{%1,%2};" : "=l"(d) : "f"(a), "f"(b)); return d;
}
__device__ __forceinline__ void upk(ull s, float& a, float& b) {
    asm("mov.b64 {%0,%1},%2;" : "=f"(a), "=f"(b) : "l"(s));
}
__device__ __forceinline__ ull f2fma(ull a, ull b, ull c) {
    ull d; asm("fma.rn.f32x2 %0,%1,%2,%3;" : "=l"(d) : "l"(a), "l"(b), "l"(c)); return d;
}
__device__ __forceinline__ ull f2add(ull a, ull b) {
    ull d; asm("add.rn.f32x2 %0,%1,%2;" : "=l"(d) : "l"(a), "l"(b)); return d;
}
__device__ __forceinline__ unsigned senc(float d) {
    unsigned u = __float_as_uint(d);
    unsigned mask = ((unsigned)(((int)u) >> 31)) | 0x80000000u;
    return u ^ mask;
}

// scratch (device globals — no runtime allocation)
__device__ ull    g_q2[BN*32];
__device__ ull    g_k2[BN*32];
__device__ ull    g_v2[BN*32];
__device__ int    g_idx[BN*KK];
__device__ float4 g_pos4[BN];
__device__ float4 s_pos4g[BN];
__device__ int    s_oidxg[BN];

#define QPB 16
#define NBINS 512
#define NCH 256      // 32-candidate chunks per batch

__device__ unsigned g_hist[BB][NBINS];
__device__ unsigned g_curs[BB][NBINS];
__device__ unsigned g_w2min[BB], g_w2max[BB];
__device__ float    g_maxbelow32[BB][NCH + 1];  // max radius over positions < c*32
__device__ float    g_minabove32[BB][NCH + 1];  // min radius over positions >= c*32

// ---------------------------------------------------------------------------
__global__ void init_kernel() {
    int b = blockIdx.x, tid = threadIdx.x;
    g_hist[b][tid] = 0;
    if (tid == 0) { g_w2min[b] = 0xFFFFFFFFu; g_w2max[b] = 0u; }
}

__global__ void prep_kernel(const float* __restrict__ pos) {
    __shared__ unsigned smin[8], smax[8];
    int i = blockIdx.x * 256 + threadIdx.x;
    int b = i / NN;
    float x = pos[3 * i], y = pos[3 * i + 1], z = pos[3 * i + 2];
    float w = fmaf(z, z, fmaf(y, y, x * x));
    g_pos4[i] = make_float4(x, y, z, w);
    unsigned wb = __float_as_uint(w);
    unsigned mn = wb, mx = wb;
#pragma unroll
    for (int d = 16; d > 0; d >>= 1) {
        mn = min(mn, __shfl_down_sync(0xffffffffu, mn, d));
        mx = max(mx, __shfl_down_sync(0xffffffffu, mx, d));
    }
    int lane = threadIdx.x & 31, wrp = threadIdx.x >> 5;
    if (lane == 0) { smin[wrp] = mn; smax[wrp] = mx; }
    __syncthreads();
    if (threadIdx.x == 0) {
        unsigned bmn = smin[0], bmx = smax[0];
        for (int k = 1; k < 8; k++) { bmn = min(bmn, smin[k]); bmx = max(bmx, smax[k]); }
        atomicMin(&g_w2min[b], bmn);
        atomicMax(&g_w2max[b], bmx);
    }
}

__device__ __forceinline__ int rbin(float r, float rmin, float inv) {
    int bin = (int)((r - rmin) * inv);
    return min(max(bin, 0), NBINS - 1);
}

__global__ void hist_kernel() {
    int i = blockIdx.x * 256 + threadIdx.x;
    int b = i / NN;
    float rmin = sqrtf(__uint_as_float(g_w2min[b]));
    float rmax = sqrtf(__uint_as_float(g_w2max[b]));
    float inv = (rmax > rmin) ? (float)NBINS / (rmax - rmin) : 0.f;
    float r = sqrtf(g_pos4[i].w);
    atomicAdd(&g_hist[b][rbin(r, rmin, inv)], 1u);
}

__global__ void scan_kernel() {
    __shared__ unsigned sh[NBINS];
    int b = blockIdx.x, tid = threadIdx.x;
    sh[tid] = g_hist[b][tid];
    __syncthreads();
    for (int off = 1; off < NBINS; off <<= 1) {
        unsigned v = (tid >= off) ? sh[tid - off] : 0u;
        __syncthreads();
        sh[tid] += v;
        __syncthreads();
    }
    g_curs[b][tid] = sh[tid] - g_hist[b][tid];
}

__global__ void scatter_kernel() {
    int i = blockIdx.x * 256 + threadIdx.x;
    int b = i / NN;
    float rmin = sqrtf(__uint_as_float(g_w2min[b]));
    float rmax = sqrtf(__uint_as_float(g_w2max[b]));
    float inv = (rmax > rmin) ? (float)NBINS / (rmax - rmin) : 0.f;
    float4 p = g_pos4[i];
    float r = sqrtf(p.w);
    unsigned pos = atomicAdd(&g_curs[b][rbin(r, rmin, inv)], 1u);
    s_pos4g[(size_t)b * NN + pos] = p;
    s_oidxg[(size_t)b * NN + pos] = i - b * NN;
}

// exact per-chunk (32 positions) radius min/max -> prefix max / suffix min.
__global__ void __launch_bounds__(1024) bounds_kernel() {
    __shared__ unsigned tmin[NCH], tmax[NCH];
    int b = blockIdx.x, tid = threadIdx.x;
    if (tid < NCH) { tmin[tid] = 0xFFFFFFFFu; tmax[tid] = 0u; }
    __syncthreads();
    unsigned mn = 0xFFFFFFFFu, mx = 0u;
    int base = tid * 8;
    int t = base >> 5;
#pragma unroll
    for (int e = 0; e < 8; e++) {
        unsigned wb = __float_as_uint(s_pos4g[(size_t)b * NN + base + e].w);
        mn = min(mn, wb);
        mx = max(mx, wb);
    }
    atomicMin(&tmin[t], mn);
    atomicMax(&tmax[t], mx);
    __syncthreads();
    if (tid == 0) {
        float runmax = 0.f;
        for (int k = 0; k <= NCH; k++) {
            g_maxbelow32[b][k] = (k == 0) ? 0.f : runmax;
            if (k < NCH) runmax = fmaxf(runmax, sqrtf(__uint_as_float(tmax[k])));
        }
        float runmin = FLT_MAX;
        for (int k = NCH; k >= 0; k--) {
            g_minabove32[b][k] = runmin;
            if (k > 0) runmin = fminf(runmin, sqrtf(__uint_as_float(tmin[k - 1])));
        }
    }
}

// ---------------------------------------------------------------------------
// Kernel 1: x = feat@emb_w + emb_b ; q/k/v = x@wq/wk/wv.  (R13-exact)
// ---------------------------------------------------------------------------
#define PW 4
__global__ void __launch_bounds__(128) proj_kernel(
        const float* __restrict__ feat,
        const float* __restrict__ emb_w, const float* __restrict__ emb_b,
        const float* __restrict__ wq, const float* __restrict__ wk,
        const float* __restrict__ wv) {
    extern __shared__ ull pu[];
    ull* we2 = pu;
    ull* wq2 = pu + 2048;
    ull* wk2 = pu + 4096;
    ull* wv2 = pu + 6144;
    ull* Sbase = pu + 8192;
    ull* ebp = Sbase + PW * 576;

    int tid = threadIdx.x, lane = tid & 31, w = tid >> 5;
    for (int e = tid; e < 2048; e += 128) {
        int j = e >> 5, l2 = e & 31;
        we2[e] = pk(emb_w[j * 64 + l2], emb_w[j * 64 + l2 + 32]);
        wq2[e] = pk(wq[j * 64 + l2],   wq[j * 64 + l2 + 32]);
        wk2[e] = pk(wk[j * 64 + l2],   wk[j * 64 + l2 + 32]);
        wv2[e] = pk(wv[j * 64 + l2],   wv[j * 64 + l2 + 32]);
    }
    if (tid < 32) ebp[tid] = pk(emb_b[tid], emb_b[tid + 32]);

    int rows = (blockIdx.x * PW + w) * 16;
    ull* S = Sbase + w * 576;

#pragma unroll
    for (int rp = 0; rp < 8; rp++) {
        const float* f0 = feat + (size_t)(rows + 2 * rp) * 64;
        const float* f1 = f0 + 64;
        S[lane * 9 + rp]        = pk(f0[lane],      f1[lane]);
        S[(lane + 32) * 9 + rp] = pk(f0[lane + 32], f1[lane + 32]);
    }
    __syncthreads();

    ull xL[8], xH[8];
    {
        float bl, bh;
        upk(ebp[lane], bl, bh);
        ull bl2 = pk(bl, bl), bh2 = pk(bh, bh);
#pragma unroll
        for (int rp = 0; rp < 8; rp++) { xL[rp] = bl2; xH[rp] = bh2; }
    }
#pragma unroll 4
    for (int j = 0; j < 64; j++) {
        ull wp = we2[j * 32 + lane];
        float wl, wh;
        upk(wp, wl, wh);
        ull wl2 = pk(wl, wl), wh2 = pk(wh, wh);
        const ull* s = S + j * 9;
#pragma unroll
        for (int rp = 0; rp < 8; rp++) {
            ull s2 = s[rp];
            xL[rp] = f2fma(s2, wl2, xL[rp]);
            xH[rp] = f2fma(s2, wh2, xH[rp]);
        }
    }
    __syncwarp();
#pragma unroll
    for (int rp = 0; rp < 8; rp++) {
        S[lane * 9 + rp]        = xL[rp];
        S[(lane + 32) * 9 + rp] = xH[rp];
    }
    __syncwarp();

    ull qL[8], qH[8], kL[8], kH[8], vL[8], vH[8];
#pragma unroll
    for (int rp = 0; rp < 8; rp++) {
        qL[rp] = qH[rp] = kL[rp] = kH[rp] = vL[rp] = vH[rp] = 0ull;
    }
#pragma unroll 2
    for (int j = 0; j < 64; j++) {
        float a, b;
        upk(wq2[j * 32 + lane], a, b);
        ull wql = pk(a, a), wqh = pk(b, b);
        upk(wk2[j * 32 + lane], a, b);
        ull wkl = pk(a, a), wkh = pk(b, b);
        upk(wv2[j * 32 + lane], a, b);
        ull wvl = pk(a, a), wvh = pk(b, b);
        const ull* s = S + j * 9;
#pragma unroll
        for (int rp = 0; rp < 8; rp++) {
            ull s2 = s[rp];
            qL[rp] = f2fma(s2, wql, qL[rp]);
            qH[rp] = f2fma(s2, wqh, qH[rp]);
            kL[rp] = f2fma(s2, wkl, kL[rp]);
            kH[rp] = f2fma(s2, wkh, kH[rp]);
            vL[rp] = f2fma(s2, wvl, vL[rp]);
            vH[rp] = f2fma(s2, wvh, vH[rp]);
        }
    }

#pragma unroll
    for (int rp = 0; rp < 8; rp++) {
        size_t r0 = (size_t)(rows + 2 * rp) * 32 + lane;
        size_t r1 = r0 + 32;
        float a0, a1, b0, b1;
        upk(qL[rp], a0, a1); upk(qH[rp], b0, b1);
        g_q2[r0] = pk(a0, b0); g_q2[r1] = pk(a1, b1);
        upk(kL[rp], a0, a1); upk(kH[rp], b0, b1);
        g_k2[r0] = pk(a0, b0); g_k2[r1] = pk(a1, b1);
        upk(vL[rp], a0, a1); upk(vH[rp], b0, b1);
        g_v2[r0] = pk(a0, b0); g_v2[r1] = pk(a1, b1);
    }
}

// ---------------------------------------------------------------------------
// Kernel 2: KNN — warp-independent radius-band expansion at 32-candidate
// granularity, direct LDG (no smem tiles, NO __syncthreads). Ballot/u64-flush
// machinery byte-identical to validated R9/R13. Bound checks are warp-uniform
// (theta, rq uniform). Selection order-independent -> exact same top-16 set.
// ---------------------------------------------------------------------------
#define FSLOTS 64

__device__ __noinline__ void knn_flush(ull* kd, int& bc, float& theta, int lane) {
    int n = 16 + bc;
    ull k0 = (lane < n) ? kd[lane] : ~0ull;
    ull k1 = (lane + 32 < n) ? kd[lane + 32] : ~0ull;
    int r0 = 0, r1 = 0;
    for (int j = 0; j < n; j++) {
        ull kj = kd[j];
        r0 += (kj < k0);
        r1 += (kj < k1);
    }
    __syncwarp();
    if (r0 < 16) kd[r0] = k0;
    if (r1 < 16) kd[r1] = k1;
    __syncwarp();
    unsigned hi = (unsigned)(kd[15] >> 32);
    unsigned u = (hi & 0x80000000u) ? (hi ^ 0x80000000u) : ~hi;
    theta = __uint_as_float(u);
    bc = 0;
}

__device__ __forceinline__ void knn_scan32(
        const float4* sp, const int* soi, int t, float4 qv0, float4 qv1,
        ull* kd0, ull* kd1, int& bc0, int& bc1, float& th0, float& th1, int lane) {
    float4 c = __ldg(&sp[t * 32 + lane]);
    float dot0 = fmaf(qv0.z, c.z, fmaf(qv0.y, c.y, qv0.x * c.x));
    float dot1 = fmaf(qv1.z, c.z, fmaf(qv1.y, c.y, qv1.x * c.x));
    float d20 = fmaf(-2.f, dot0, qv0.w + c.w);
    float d21 = fmaf(-2.f, dot1, qv1.w + c.w);
    bool a0 = d20 < th0;
    bool a1 = d21 < th1;
    if (__ballot_sync(0xffffffffu, a0 | a1)) {
        if (bc0 > 16) { knn_flush(kd0, bc0, th0, lane); a0 = d20 < th0; }
        if (bc1 > 16) { knn_flush(kd1, bc1, th1, lane); a1 = d21 < th1; }
        unsigned m0 = __ballot_sync(0xffffffffu, a0);
        unsigned m1 = __ballot_sync(0xffffffffu, a1);
        int oi = __ldg(&soi[t * 32 + lane]);
        if (m0) {
            int off = __popc(m0 & ((1u << lane) - 1u));
            if (a0) kd0[16 + bc0 + off] = (((ull)senc(d20)) << 32) | (unsigned)oi;
            bc0 += __popc(m0);
        }
        if (m1) {
            int off = __popc(m1 & ((1u << lane) - 1u));
            if (a1) kd1[16 + bc1 + off] = (((ull)senc(d21)) << 32) | (unsigned)oi;
            bc1 += __popc(m1);
        }
    }
}

__global__ void __launch_bounds__(256) knn_kernel() {
    __shared__ ull kbuf[16 * FSLOTS];   // 8 KB static

    int tid = threadIdx.x, lane = tid & 31, w = tid >> 5;
    int b = blockIdx.y;
    int p0 = blockIdx.x * QPB + 2 * w;
    int p1 = p0 + 1;
    const float4* sp = s_pos4g + (size_t)b * NN;
    const int*   soi = s_oidxg + (size_t)b * NN;
    float4 qv0 = sp[p0], qv1 = sp[p1];
    float rq0 = sqrtf(qv0.w), rq1 = sqrtf(qv1.w);
    int oq0 = soi[p0], oq1 = soi[p1];

    ull* kd0 = kbuf + (w * 2 + 0) * FSLOTS;
    ull* kd1 = kbuf + (w * 2 + 1) * FSLOTS;
    if (lane < 16) {
        kd0[lane] = (((ull)0xFF7FFFFFu) << 32) | (unsigned)lane;
        kd1[lane] = (((ull)0xFF7FFFFFu) << 32) | (unsigned)lane;
    }
    __syncwarp();

    float th0 = FLT_MAX, th1 = FLT_MAX;
    int bc0 = 0, bc1 = 0;
    int c = p0 >> 5;      // home chunk (contains both queries)

    // prime theta exactly from home chunk (32 candidates, incl. the queries)
    {
        float4 cc = __ldg(&sp[c * 32 + lane]);
        float dot0 = fmaf(qv0.z, cc.z, fmaf(qv0.y, cc.y, qv0.x * cc.x));
        float dot1 = fmaf(qv1.z, cc.z, fmaf(qv1.y, cc.y, qv1.x * cc.x));
        float d20 = fmaf(-2.f, dot0, qv0.w + cc.w);
        float d21 = fmaf(-2.f, dot1, qv1.w + cc.w);
        int oi = __ldg(&soi[c * 32 + lane]);
        kd0[16 + lane] = (((ull)senc(d20)) << 32) | (unsigned)oi;
        kd1[16 + lane] = (((ull)senc(d21)) << 32) | (unsigned)oi;
        __syncwarp();
        bc0 = 32; knn_flush(kd0, bc0, th0, lane);
        bc1 = 32; knn_flush(kd1, bc1, th1, lane);
    }

    const float* mb = g_maxbelow32[b];
    const float* ma = g_minabove32[b];
    int lo = c, hi = c, toggle = 0;
    while (true) {
        bool ndn = false, nup = false;
        if (lo > 0) {
            float rb = mb[lo];
            float g0 = rq0 - rb, g1 = rq1 - rb;
            ndn = !((g0 > 0.f && g0 * g0 >= th0 * 1.0001f) &&
                    (g1 > 0.f && g1 * g1 >= th1 * 1.0001f));
        }
        if (hi < NCH - 1) {
            float ra = ma[hi + 1];
            float g0 = ra - rq0, g1 = ra - rq1;
            nup = !((g0 > 0.f && g0 * g0 >= th0 * 1.0001f) &&
                    (g1 > 0.f && g1 * g1 >= th1 * 1.0001f));
        }
        if (!ndn && !nup) break;
        int t;
        if (nup && (!ndn || toggle == 0)) { t = ++hi; toggle = 1; }
        else                              { t = --lo; toggle = 0; }
        knn_scan32(sp, soi, t, qv0, qv1, kd0, kd1, bc0, bc1, th0, th1, lane);
    }
    if (bc0 > 0) knn_flush(kd0, bc0, th0, lane);
    if (bc1 > 0) knn_flush(kd1, bc1, th1, lane);
    if (lane < 16) {
        g_idx[((size_t)b * NN + oq0) * KK + lane] = (int)(unsigned)(kd0[lane] & 0xFFFFFFFFu);
        g_idx[((size_t)b * NN + oq1) * KK + lane] = (int)(unsigned)(kd1[lane] & 0xFFFFFFFFu);
    }
}

// ---------------------------------------------------------------------------
// Kernel 3: fused posenc + attn MLPs + softmax + combine + out projection.
// (R13/R9-exact scalar FFMA2 version; measured 165-166 us)
// ---------------------------------------------------------------------------
#define AQ 8
#define SQSTRIDE 640

__device__ __forceinline__ void mv16x64(const ull* __restrict__ Sq,
                                        const ulonglong2* __restrict__ w4, int l,
                                        ull aL[8], ull aH[8]) {
#pragma unroll
    for (int kp = 0; kp < 8; kp++) { aL[kp] = 0ull; aH[kp] = 0ull; }
#pragma unroll 4
    for (int jp = 0; jp < 32; jp++) {
        ulonglong2 wpp = w4[jp * 32 + l];
        {
            float wl, wh;
            upk(wpp.x, wl, wh);
            ull wl2 = pk(wl, wl), wh2 = pk(wh, wh);
            const ulonglong2* s = (const ulonglong2*)(Sq + (2 * jp) * 10);
#pragma unroll
            for (int kp2 = 0; kp2 < 4; kp2++) {
                ulonglong2 sv = s[kp2];
                aL[2 * kp2]     = f2fma(sv.x, wl2, aL[2 * kp2]);
                aH[2 * kp2]     = f2fma(sv.x, wh2, aH[2 * kp2]);
                aL[2 * kp2 + 1] = f2fma(sv.y, wl2, aL[2 * kp2 + 1]);
                aH[2 * kp2 + 1] = f2fma(sv.y, wh2, aH[2 * kp2 + 1]);
            }
        }
        {
            float wl, wh;
            upk(wpp.y, wl, wh);
            ull wl2 = pk(wl, wl), wh2 = pk(wh, wh);
            const ulonglong2* s = (const ulonglong2*)(Sq + (2 * jp + 1) * 10);
#pragma unroll
            for (int kp2 = 0; kp2 < 4; kp2++) {
                ulonglong2 sv = s[kp2];
                aL[2 * kp2]     = f2fma(sv.x, wl2, aL[2 * kp2]);
                aH[2 * kp2]     = f2fma(sv.x, wh2, aH[2 * kp2]);
                aL[2 * kp2 + 1] = f2fma(sv.y, wl2, aL[2 * kp2 + 1]);
                aH[2 * kp2 + 1] = f2fma(sv.y, wh2, aH[2 * kp2 + 1]);
            }
        }
    }
}

__global__ void __launch_bounds__(256) attn_kernel(
        const float* __restrict__ feat,
        const float* __restrict__ pe_w1, const float* __restrict__ pe_b1,
        const float* __restrict__ pe_w2, const float* __restrict__ pe_b2,
        const float* __restrict__ at_w1, const float* __restrict__ at_b1,
        const float* __restrict__ at_w2, const float* __restrict__ at_b2,
        const float* __restrict__ out_w, const float* __restrict__ out_b,
        float* __restrict__ out) {
    extern __shared__ ull smu[];
    ulonglong2* w4_pe2 = (ulonglong2*)smu;
    ulonglong2* w4_at1 = (ulonglong2*)(smu + 2048);
    ulonglong2* w4_at2 = (ulonglong2*)(smu + 4096);
    ull* Sp2    = smu + 6144;
    float* s_pe1 = (float*)(Sp2 + AQ * SQSTRIDE);
    float* s_b   = s_pe1 + 192;
    float* relb  = s_b + 320;
    float* resb  = relb + AQ * 64;
    int*   idxb  = (int*)(resb + AQ * 64);

    int tid = threadIdx.x;
    for (int e = tid; e < 1024; e += 256) {
        int jp = e >> 5, l2 = e & 31;
        int j0 = 2 * jp, j1 = 2 * jp + 1;
        w4_pe2[e] = make_ulonglong2(pk(pe_w2[j0 * 64 + l2], pe_w2[j0 * 64 + l2 + 32]),
                                    pk(pe_w2[j1 * 64 + l2], pe_w2[j1 * 64 + l2 + 32]));
        w4_at1[e] = make_ulonglong2(pk(at_w1[j0 * 64 + l2], at_w1[j0 * 64 + l2 + 32]),
                                    pk(at_w1[j1 * 64 + l2], at_w1[j1 * 64 + l2 + 32]));
        w4_at2[e] = make_ulonglong2(pk(at_w2[j0 * 64 + l2], at_w2[j0 * 64 + l2 + 32]),
                                    pk(at_w2[j1 * 64 + l2], at_w2[j1 * 64 + l2 + 32]));
    }
    if (tid < 192) s_pe1[tid] = pe_w1[tid];
    if (tid < 64) {
        s_b[tid]       = pe_b1[tid];
        s_b[64 + tid]  = pe_b2[tid];
        s_b[128 + tid] = at_b1[tid];
        s_b[192 + tid] = at_b2[tid];
        s_b[256 + tid] = out_b[tid];
    }

    int wid = tid >> 5;
    int l   = tid & 31;
    int g   = blockIdx.x * AQ + wid;
    int bbase = g & ~(NN - 1);

    float q_lo, q_hi;
    upk(g_q2[(size_t)g * 32 + l], q_lo, q_hi);

    if (l < KK) {
        int ii = g_idx[(size_t)g * KK + l];
        idxb[wid * KK + l] = ii;
        float4 np = g_pos4[bbase + ii];
        float4 qp = g_pos4[g];
        relb[(wid * KK + l) * 4 + 0] = np.x - qp.x;
        relb[(wid * KK + l) * 4 + 1] = np.y - qp.y;
        relb[(wid * KK + l) * 4 + 2] = np.z - qp.z;
    }
    __syncthreads();

    ull* Sq = Sp2 + wid * SQSTRIDE;

    // Stage A: pe1 = relu(rel @ pe_w1 + pe_b1)
    {
        float w0l = s_pe1[l],      w1l = s_pe1[64 + l],  w2l = s_pe1[128 + l];
        float w0h = s_pe1[l + 32], w1h = s_pe1[96 + l],  w2h = s_pe1[160 + l];
        float b1l = s_b[l], b1h = s_b[l + 32];
#pragma unroll
        for (int kp = 0; kp < 8; kp++) {
            const float* ra = relb + (wid * KK + 2 * kp) * 4;
            const float* rb = ra + 4;
            float pa = fmaxf(fmaf(ra[2], w2l, fmaf(ra[1], w1l, fmaf(ra[0], w0l, b1l))), 0.f);
            float pb = fmaxf(fmaf(rb[2], w2l, fmaf(rb[1], w1l, fmaf(rb[0], w0l, b1l))), 0.f);
            Sq[l * 10 + kp] = pk(pa, pb);
            float qa = fmaxf(fmaf(ra[2], w2h, fmaf(ra[1], w1h, fmaf(ra[0], w0h, b1h))), 0.f);
            float qb = fmaxf(fmaf(rb[2], w2h, fmaf(rb[1], w1h, fmaf(rb[0], w0h, b1h))), 0.f);
            Sq[(l + 32) * 10 + kp] = pk(qa, qb);
        }
    }
    __syncwarp();

    // Stage B: posenc = pe1 @ pe_w2 + pe_b2
    ull penL[8], penH[8];
    mv16x64(Sq, w4_pe2, l, penL, penH);
    {
        ull b2l = pk(s_b[64 + l], s_b[64 + l]);
        ull b2h = pk(s_b[64 + l + 32], s_b[64 + l + 32]);
#pragma unroll
        for (int kp = 0; kp < 8; kp++) {
            penL[kp] = f2add(penL[kp], b2l);
            penH[kp] = f2add(penH[kp], b2h);
        }
    }
    __syncwarp();

    // Stage C: h = q - k_feat + posenc
#pragma unroll
    for (int kp = 0; kp < 8; kp++) {
        int i0 = idxb[wid * KK + 2 * kp];
        int i1 = idxb[wid * KK + 2 * kp + 1];
        float k0l, k0h, k1l, k1h;
        upk(g_k2[(size_t)(bbase + i0) * 32 + l], k0l, k0h);
        upk(g_k2[(size_t)(bbase + i1) * 32 + l], k1l, k1h);
        float p0, p1;
        upk(penL[kp], p0, p1);
        Sq[l * 10 + kp] = pk(q_lo - k0l + p0, q_lo - k1l + p1);
        upk(penH[kp], p0, p1);
        Sq[(l + 32) * 10 + kp] = pk(q_hi - k0h + p0, q_hi - k1h + p1);
    }
    __syncwarp();

    // Stage D: a1 = relu(h @ at_w1 + at_b1)
    ull aL[8], aH[8];
    mv16x64(Sq, w4_at1, l, aL, aH);
    __syncwarp();
    {
        float bl = s_b[128 + l], bh = s_b[128 + l + 32];
#pragma unroll
        for (int kp = 0; kp < 8; kp++) {
            float x, y;
            upk(aL[kp], x, y);
            Sq[l * 10 + kp] = pk(fmaxf(x + bl, 0.f), fmaxf(y + bl, 0.f));
            upk(aH[kp], x, y);
            Sq[(l + 32) * 10 + kp] = pk(fmaxf(x + bh, 0.f), fmaxf(y + bh, 0.f));
        }
    }
    __syncwarp();

    // Stage E: logits = (a1 @ at_w2 + at_b2) / 8
    mv16x64(Sq, w4_at2, l, aL, aH);
    float el[KK], eh[KK];
    {
        float bl = s_b[192 + l], bh = s_b[192 + l + 32];
#pragma unroll
        for (int kp = 0; kp < 8; kp++) {
            float x, y;
            upk(aL[kp], x, y);
            el[2 * kp] = (x + bl) * 0.125f; el[2 * kp + 1] = (y + bl) * 0.125f;
            upk(aH[kp], x, y);
            eh[2 * kp] = (x + bh) * 0.125f; eh[2 * kp + 1] = (y + bh) * 0.125f;
        }
    }

    // softmax over K per channel + combine with (v + posenc)
    float ml = el[0], mh = eh[0];
#pragma unroll
    for (int k = 1; k < KK; k++) { ml = fmaxf(ml, el[k]); mh = fmaxf(mh, eh[k]); }
    float sl = 0.f, sh = 0.f;
#pragma unroll
    for (int k = 0; k < KK; k++) {
        el[k] = __expf(el[k] - ml); sl += el[k];
        eh[k] = __expf(eh[k] - mh); sh += eh[k];
    }
    float il = 1.f / sl, ih = 1.f / sh;
    float res_lo = 0.f, res_hi = 0.f;
#pragma unroll
    for (int kp = 0; kp < 8; kp++) {
        int i0 = idxb[wid * KK + 2 * kp];
        int i1 = idxb[wid * KK + 2 * kp + 1];
        float v0l, v0h, v1l, v1h;
        upk(g_v2[(size_t)(bbase + i0) * 32 + l], v0l, v0h);
        upk(g_v2[(size_t)(bbase + i1) * 32 + l], v1l, v1h);
        float p0, p1;
        upk(penL[kp], p0, p1);
        res_lo = fmaf(el[2 * kp] * il,     v0l + p0, res_lo);
        res_lo = fmaf(el[2 * kp + 1] * il, v1l + p1, res_lo);
        upk(penH[kp], p0, p1);
        res_hi = fmaf(eh[2 * kp] * ih,     v0h + p0, res_hi);
        res_hi = fmaf(eh[2 * kp + 1] * ih, v1h + p1, res_hi);
    }
    resb[wid * CC + l] = res_lo;
    resb[wid * CC + l + 32] = res_hi;
    __syncwarp();

    // final: out = res @ out_w + out_b + features (out_w via L1)
    {
        float ol = s_b[256 + l], oh = s_b[256 + l + 32];
#pragma unroll 4
        for (int j = 0; j < 64; j++) {
            float rj = resb[wid * CC + j];
            ol = fmaf(rj, __ldg(&out_w[j * 64 + l]), ol);
            oh = fmaf(rj, __ldg(&out_w[j * 64 + l + 32]), oh);
        }
        out[(size_t)g * CC + l]      = ol + feat[(size_t)g * CC + l];
        out[(size_t)g * CC + l + 32] = oh + feat[(size_t)g * CC + l + 32];
    }
}

// ---------------------------------------------------------------------------
extern "C" void kernel_launch(void* const* d_in, const int* in_sizes, int n_in,
                              void* d_out, int out_size) {
    const float* pos   = (const float*)d_in[0];
    const float* feat  = (const float*)d_in[1];
    const float* emb_w = (const float*)d_in[2];
    const float* emb_b = (const float*)d_in[3];
    const float* wq    = (const float*)d_in[4];
    const float* wk    = (const float*)d_in[5];
    const float* wv    = (const float*)d_in[6];
    const float* pe_w1 = (const float*)d_in[7];
    const float* pe_b1 = (const float*)d_in[8];
    const float* pe_w2 = (const float*)d_in[9];
    const float* pe_b2 = (const float*)d_in[10];
    const float* at_w1 = (const float*)d_in[11];
    const float* at_b1 = (const float*)d_in[12];
    const float* at_w2 = (const float*)d_in[13];
    const float* at_b2 = (const float*)d_in[14];
    const float* out_w = (const float*)d_in[15];
    const float* out_b = (const float*)d_in[16];
    float* out = (float*)d_out;

    int proj_smem = (8192 + PW * 576 + 32) * 8;
    int attn_smem = (6144 + AQ * SQSTRIDE) * 8
                  + (192 + 320 + AQ * 64 * 2) * 4 + AQ * KK * 4;
    cudaFuncSetAttribute(proj_kernel, cudaFuncAttributeMaxDynamicSharedMemorySize, proj_smem);
    cudaFuncSetAttribute(attn_kernel, cudaFuncAttributeMaxDynamicSharedMemorySize, attn_smem);

    init_kernel<<<BB, NBINS>>>();
    prep_kernel<<<BN / 256, 256>>>(pos);
    hist_kernel<<<BN / 256, 256>>>();
    scan_kernel<<<BB, NBINS>>>();
    scatter_kernel<<<BN / 256, 256>>>();
    bounds_kernel<<<BB, 1024>>>();
    proj_kernel<<<BN / (PW * 16), 128, proj_smem>>>(feat, emb_w, emb_b, wq, wk, wv);
    knn_kernel<<<dim3(NN / QPB, BB), 256>>>();
    attn_kernel<<<BN / AQ, 256, attn_smem>>>(feat, pe_w1, pe_b1, pe_w2, pe_b2,
                                             at_w1, at_b1, at_w2, at_b2, out_w, out_b, out);
}

// round 16
// speedup vs baseline: 1.1149x; 1.1149x over previous
#include <cuda_runtime.h>
#include <math.h>
#include <float.h>

#define BB 2
#define NN 8192
#define KK 16
#define CC 64
#define BN (BB*NN)

typedef unsigned long long ull;

__device__ __forceinline__ ull pk(float a, float b) {
    ull d; asm("mov.b64 %0,{%1,%2};" : "=l"(d) : "f"(a), "f"(b)); return d;
}
__device__ __forceinline__ void upk(ull s, float& a, float& b) {
    asm("mov.b64 {%0,%1},%2;" : "=f"(a), "=f"(b) : "l"(s));
}
__device__ __forceinline__ ull f2fma(ull a, ull b, ull c) {
    ull d; asm("fma.rn.f32x2 %0,%1,%2,%3;" : "=l"(d) : "l"(a), "l"(b), "l"(c)); return d;
}
__device__ __forceinline__ ull f2add(ull a, ull b) {
    ull d; asm("add.rn.f32x2 %0,%1,%2;" : "=l"(d) : "l"(a), "l"(b)); return d;
}
__device__ __forceinline__ unsigned senc(float d) {
    unsigned u = __float_as_uint(d);
    unsigned mask = ((unsigned)(((int)u) >> 31)) | 0x80000000u;
    return u ^ mask;
}

// scratch (device globals — no runtime allocation)
__device__ ull    g_q2[BN*32];
__device__ ull    g_k2[BN*32];
__device__ ull    g_v2[BN*32];
__device__ int    g_idx[BN*KK];
__device__ float4 g_pos4[BN];
__device__ float4 s_pos4g[BN];
__device__ int    s_oidxg[BN];

#define TS 256
#define NT (NN/TS)   // 32 tiles
#define QPB 8        // binned queries per knn block (4 warps)
#define NBINS 512

__device__ unsigned g_hist[BB][NBINS];
__device__ unsigned g_curs[BB][NBINS];
__device__ unsigned g_w2min[BB], g_w2max[BB];
__device__ float    g_maxbelow[BB][NT + 1];
__device__ float    g_minabove[BB][NT + 1];

// ---------------------------------------------------------------------------
__global__ void init_kernel() {
    int b = blockIdx.x, tid = threadIdx.x;
    g_hist[b][tid] = 0;
    if (tid == 0) { g_w2min[b] = 0xFFFFFFFFu; g_w2max[b] = 0u; }
}

__global__ void prep_kernel(const float* __restrict__ pos) {
    __shared__ unsigned smin[8], smax[8];
    int i = blockIdx.x * 256 + threadIdx.x;
    int b = i / NN;
    float x = pos[3 * i], y = pos[3 * i + 1], z = pos[3 * i + 2];
    float w = fmaf(z, z, fmaf(y, y, x * x));
    g_pos4[i] = make_float4(x, y, z, w);
    unsigned wb = __float_as_uint(w);
    unsigned mn = wb, mx = wb;
#pragma unroll
    for (int d = 16; d > 0; d >>= 1) {
        mn = min(mn, __shfl_down_sync(0xffffffffu, mn, d));
        mx = max(mx, __shfl_down_sync(0xffffffffu, mx, d));
    }
    int lane = threadIdx.x & 31, wrp = threadIdx.x >> 5;
    if (lane == 0) { smin[wrp] = mn; smax[wrp] = mx; }
    __syncthreads();
    if (threadIdx.x == 0) {
        unsigned bmn = smin[0], bmx = smax[0];
        for (int k = 1; k < 8; k++) { bmn = min(bmn, smin[k]); bmx = max(bmx, smax[k]); }
        atomicMin(&g_w2min[b], bmn);
        atomicMax(&g_w2max[b], bmx);
    }
}

__device__ __forceinline__ int rbin(float r, float rmin, float inv) {
    int bin = (int)((r - rmin) * inv);
    return min(max(bin, 0), NBINS - 1);
}

__global__ void hist_kernel() {
    int i = blockIdx.x * 256 + threadIdx.x;
    int b = i / NN;
    float rmin = sqrtf(__uint_as_float(g_w2min[b]));
    float rmax = sqrtf(__uint_as_float(g_w2max[b]));
    float inv = (rmax > rmin) ? (float)NBINS / (rmax - rmin) : 0.f;
    float r = sqrtf(g_pos4[i].w);
    atomicAdd(&g_hist[b][rbin(r, rmin, inv)], 1u);
}

__global__ void scan_kernel() {
    __shared__ unsigned sh[NBINS];
    int b = blockIdx.x, tid = threadIdx.x;
    sh[tid] = g_hist[b][tid];
    __syncthreads();
    for (int off = 1; off < NBINS; off <<= 1) {
        unsigned v = (tid >= off) ? sh[tid - off] : 0u;
        __syncthreads();
        sh[tid] += v;
        __syncthreads();
    }
    g_curs[b][tid] = sh[tid] - g_hist[b][tid];
}

__global__ void scatter_kernel() {
    int i = blockIdx.x * 256 + threadIdx.x;
    int b = i / NN;
    float rmin = sqrtf(__uint_as_float(g_w2min[b]));
    float rmax = sqrtf(__uint_as_float(g_w2max[b]));
    float inv = (rmax > rmin) ? (float)NBINS / (rmax - rmin) : 0.f;
    float4 p = g_pos4[i];
    float r = sqrtf(p.w);
    unsigned pos = atomicAdd(&g_curs[b][rbin(r, rmin, inv)], 1u);
    s_pos4g[(size_t)b * NN + pos] = p;
    s_oidxg[(size_t)b * NN + pos] = i - b * NN;
}

__global__ void __launch_bounds__(1024) bounds_kernel() {
    __shared__ unsigned tmin[NT], tmax[NT];
    int b = blockIdx.x, tid = threadIdx.x;
    if (tid < NT) { tmin[tid] = 0xFFFFFFFFu; tmax[tid] = 0u; }
    __syncthreads();
    unsigned mn = 0xFFFFFFFFu, mx = 0u;
    int base = tid * 8;
    int t = base / TS;
#pragma unroll
    for (int e = 0; e < 8; e++) {
        unsigned wb = __float_as_uint(s_pos4g[(size_t)b * NN + base + e].w);
        mn = min(mn, wb);
        mx = max(mx, wb);
    }
    atomicMin(&tmin[t], mn);
    atomicMax(&tmax[t], mx);
    __syncthreads();
    if (tid == 0) {
        float runmax = 0.f;
        for (int k = 0; k <= NT; k++) {
            g_maxbelow[b][k] = (k == 0) ? 0.f : runmax;
            if (k < NT) runmax = fmaxf(runmax, sqrtf(__uint_as_float(tmax[k])));
        }
        float runmin = FLT_MAX;
        for (int k = NT; k >= 0; k--) {
            g_minabove[b][k] = runmin;
            if (k > 0) runmin = fminf(runmin, sqrtf(__uint_as_float(tmin[k - 1])));
        }
    }
}

// ---------------------------------------------------------------------------
// Kernel 1: x = feat@emb_w + emb_b ; q/k/v = x@wq/wk/wv.  (R13-exact)
// ---------------------------------------------------------------------------
#define PW 4
__global__ void __launch_bounds__(128) proj_kernel(
        const float* __restrict__ feat,
        const float* __restrict__ emb_w, const float* __restrict__ emb_b,
        const float* __restrict__ wq, const float* __restrict__ wk,
        const float* __restrict__ wv) {
    extern __shared__ ull pu[];
    ull* we2 = pu;
    ull* wq2 = pu + 2048;
    ull* wk2 = pu + 4096;
    ull* wv2 = pu + 6144;
    ull* Sbase = pu + 8192;
    ull* ebp = Sbase + PW * 576;

    int tid = threadIdx.x, lane = tid & 31, w = tid >> 5;
    for (int e = tid; e < 2048; e += 128) {
        int j = e >> 5, l2 = e & 31;
        we2[e] = pk(emb_w[j * 64 + l2], emb_w[j * 64 + l2 + 32]);
        wq2[e] = pk(wq[j * 64 + l2],   wq[j * 64 + l2 + 32]);
        wk2[e] = pk(wk[j * 64 + l2],   wk[j * 64 + l2 + 32]);
        wv2[e] = pk(wv[j * 64 + l2],   wv[j * 64 + l2 + 32]);
    }
    if (tid < 32) ebp[tid] = pk(emb_b[tid], emb_b[tid + 32]);

    int rows = (blockIdx.x * PW + w) * 16;
    ull* S = Sbase + w * 576;

#pragma unroll
    for (int rp = 0; rp < 8; rp++) {
        const float* f0 = feat + (size_t)(rows + 2 * rp) * 64;
        const float* f1 = f0 + 64;
        S[lane * 9 + rp]        = pk(f0[lane],      f1[lane]);
        S[(lane + 32) * 9 + rp] = pk(f0[lane + 32], f1[lane + 32]);
    }
    __syncthreads();

    ull xL[8], xH[8];
    {
        float bl, bh;
        upk(ebp[lane], bl, bh);
        ull bl2 = pk(bl, bl), bh2 = pk(bh, bh);
#pragma unroll
        for (int rp = 0; rp < 8; rp++) { xL[rp] = bl2; xH[rp] = bh2; }
    }
#pragma unroll 4
    for (int j = 0; j < 64; j++) {
        ull wp = we2[j * 32 + lane];
        float wl, wh;
        upk(wp, wl, wh);
        ull wl2 = pk(wl, wl), wh2 = pk(wh, wh);
        const ull* s = S + j * 9;
#pragma unroll
        for (int rp = 0; rp < 8; rp++) {
            ull s2 = s[rp];
            xL[rp] = f2fma(s2, wl2, xL[rp]);
            xH[rp] = f2fma(s2, wh2, xH[rp]);
        }
    }
    __syncwarp();
#pragma unroll
    for (int rp = 0; rp < 8; rp++) {
        S[lane * 9 + rp]        = xL[rp];
        S[(lane + 32) * 9 + rp] = xH[rp];
    }
    __syncwarp();

    ull qL[8], qH[8], kL[8], kH[8], vL[8], vH[8];
#pragma unroll
    for (int rp = 0; rp < 8; rp++) {
        qL[rp] = qH[rp] = kL[rp] = kH[rp] = vL[rp] = vH[rp] = 0ull;
    }
#pragma unroll 2
    for (int j = 0; j < 64; j++) {
        float a, b;
        upk(wq2[j * 32 + lane], a, b);
        ull wql = pk(a, a), wqh = pk(b, b);
        upk(wk2[j * 32 + lane], a, b);
        ull wkl = pk(a, a), wkh = pk(b, b);
        upk(wv2[j * 32 + lane], a, b);
        ull wvl = pk(a, a), wvh = pk(b, b);
        const ull* s = S + j * 9;
#pragma unroll
        for (int rp = 0; rp < 8; rp++) {
            ull s2 = s[rp];
            qL[rp] = f2fma(s2, wql, qL[rp]);
            qH[rp] = f2fma(s2, wqh, qH[rp]);
            kL[rp] = f2fma(s2, wkl, kL[rp]);
            kH[rp] = f2fma(s2, wkh, kH[rp]);
            vL[rp] = f2fma(s2, wvl, vL[rp]);
            vH[rp] = f2fma(s2, wvh, vH[rp]);
        }
    }

#pragma unroll
    for (int rp = 0; rp < 8; rp++) {
        size_t r0 = (size_t)(rows + 2 * rp) * 32 + lane;
        size_t r1 = r0 + 32;
        float a0, a1, b0, b1;
        upk(qL[rp], a0, a1); upk(qH[rp], b0, b1);
        g_q2[r0] = pk(a0, b0); g_q2[r1] = pk(a1, b1);
        upk(kL[rp], a0, a1); upk(kH[rp], b0, b1);
        g_k2[r0] = pk(a0, b0); g_k2[r1] = pk(a1, b1);
        upk(vL[rp], a0, a1); upk(vH[rp], b0, b1);
        g_v2[r0] = pk(a0, b0); g_v2[r1] = pk(a1, b1);
    }
}

// ---------------------------------------------------------------------------
// Kernel 2: KNN — R13 block-tiled radius-band expansion, with (a) QPB=8
// (4 warps/block: tighter band union, cheaper barriers, more blocks) and
// (b) double-buffered expansion flags: 2 syncs per tile decision instead
// of 4. Scan/ballot/u64-flush machinery byte-identical to validated R13.
// ---------------------------------------------------------------------------
#define FSLOTS 64

__device__ __noinline__ void knn_flush(ull* kd, int& bc, float& theta, int lane) {
    int n = 16 + bc;
    ull k0 = (lane < n) ? kd[lane] : ~0ull;
    ull k1 = (lane + 32 < n) ? kd[lane + 32] : ~0ull;
    int r0 = 0, r1 = 0;
    for (int j = 0; j < n; j++) {
        ull kj = kd[j];
        r0 += (kj < k0);
        r1 += (kj < k1);
    }
    __syncwarp();
    if (r0 < 16) kd[r0] = k0;
    if (r1 < 16) kd[r1] = k1;
    __syncwarp();
    unsigned hi = (unsigned)(kd[15] >> 32);
    unsigned u = (hi & 0x80000000u) ? (hi ^ 0x80000000u) : ~hi;
    theta = __uint_as_float(u);
    bc = 0;
}

__global__ void __launch_bounds__(128) knn_kernel() {
    extern __shared__ ull ku[];
    float4* tile = (float4*)ku;                 // TS float4 = 512 ull
    ull*    kbuf = ku + 512;                    // QPB*64 = 512 ull
    int*    tidx = (int*)(ku + 1024);           // TS ints = 128 ull
    int*    flg  = (int*)(ku + 1024 + 128);     // 4 ints (double-buffered pairs)

    int tid = threadIdx.x, lane = tid & 31, w = tid >> 5;
    int b = blockIdx.y;
    int p0 = blockIdx.x * QPB + 2 * w;
    int p1 = p0 + 1;
    const float4* sp = s_pos4g + (size_t)b * NN;
    const int*   soi = s_oidxg + (size_t)b * NN;
    float4 qv0 = sp[p0], qv1 = sp[p1];
    float rq0 = sqrtf(qv0.w), rq1 = sqrtf(qv1.w);
    int oq0 = soi[p0], oq1 = soi[p1];

    ull* kd0 = kbuf + (w * 2 + 0) * FSLOTS;
    ull* kd1 = kbuf + (w * 2 + 1) * FSLOTS;
    if (lane < 16) {
        kd0[lane] = (((ull)0xFF7FFFFFu) << 32) | (unsigned)lane;
        kd1[lane] = (((ull)0xFF7FFFFFu) << 32) | (unsigned)lane;
    }
    if (tid < 4) flg[tid] = 0;
    __syncwarp();

    float th0 = FLT_MAX, th1 = FLT_MAX;
    int bc0 = 0, bc1 = 0;
    int h = (blockIdx.x * QPB) / TS;

    // ---- home tile: load, prime theta from first 32, scan the rest ----
    for (int i = tid; i < TS; i += 128) {
        tile[i] = sp[h * TS + i];
        tidx[i] = soi[h * TS + i];
    }
    __syncthreads();
    {
        float4 c = tile[lane];
        float dot0 = fmaf(qv0.z, c.z, fmaf(qv0.y, c.y, qv0.x * c.x));
        float dot1 = fmaf(qv1.z, c.z, fmaf(qv1.y, c.y, qv1.x * c.x));
        float d20 = fmaf(-2.f, dot0, qv0.w + c.w);
        float d21 = fmaf(-2.f, dot1, qv1.w + c.w);
        int oi = tidx[lane];
        kd0[16 + lane] = (((ull)senc(d20)) << 32) | (unsigned)oi;
        kd1[16 + lane] = (((ull)senc(d21)) << 32) | (unsigned)oi;
        __syncwarp();
        bc0 = 32; knn_flush(kd0, bc0, th0, lane);
        bc1 = 32; knn_flush(kd1, bc1, th1, lane);
    }
    for (int s = 1; s < TS / 32; s++) {
        float4 c = tile[s * 32 + lane];
        float dot0 = fmaf(qv0.z, c.z, fmaf(qv0.y, c.y, qv0.x * c.x));
        float dot1 = fmaf(qv1.z, c.z, fmaf(qv1.y, c.y, qv1.x * c.x));
        float d20 = fmaf(-2.f, dot0, qv0.w + c.w);
        float d21 = fmaf(-2.f, dot1, qv1.w + c.w);
        bool a0 = d20 < th0;
        bool a1 = d21 < th1;
        if (__ballot_sync(0xffffffffu, a0 | a1)) {
            if (bc0 > 16) { knn_flush(kd0, bc0, th0, lane); a0 = d20 < th0; }
            if (bc1 > 16) { knn_flush(kd1, bc1, th1, lane); a1 = d21 < th1; }
            unsigned m0 = __ballot_sync(0xffffffffu, a0);
            unsigned m1 = __ballot_sync(0xffffffffu, a1);
            int oi = tidx[s * 32 + lane];
            if (m0) {
                int off = __popc(m0 & ((1u << lane) - 1u));
                if (a0) kd0[16 + bc0 + off] = (((ull)senc(d20)) << 32) | (unsigned)oi;
                bc0 += __popc(m0);
            }
            if (m1) {
                int off = __popc(m1 & ((1u << lane) - 1u));
                if (a1) kd1[16 + bc1 + off] = (((ull)senc(d21)) << 32) | (unsigned)oi;
                bc1 += __popc(m1);
            }
        }
    }

    // ---- outward expansion, double-buffered flags: 2 syncs/iteration ----
    int lo = h, hi = h, toggle = 0, it = 0;
    while (true) {
        int cur = (it & 1) * 2;
        bool ndn = false, nup = false;
        if (lo > 0) {
            float rb = g_maxbelow[b][lo];
            float g0 = rq0 - rb, g1 = rq1 - rb;
            if (!(g0 > 0.f && g0 * g0 >= th0 * 1.0001f)) ndn = true;
            if (!(g1 > 0.f && g1 * g1 >= th1 * 1.0001f)) ndn = true;
        }
        if (hi < NT - 1) {
            float ra = g_minabove[b][hi + 1];
            float g0 = ra - rq0, g1 = ra - rq1;
            if (!(g0 > 0.f && g0 * g0 >= th0 * 1.0001f)) nup = true;
            if (!(g1 > 0.f && g1 * g1 >= th1 * 1.0001f)) nup = true;
        }
        if (lane == 0) {
            if (ndn) atomicOr(&flg[cur + 0], 1);
            if (nup) atomicOr(&flg[cur + 1], 1);
        }
        __syncthreads();                 // sync 1: ors visible, prev scans done
        int fdn = flg[cur + 0], fup = flg[cur + 1];
        if (tid < 2) flg[(cur ^ 2) + tid] = 0;   // zero next iteration's pair
        if (!fdn && !fup) break;
        int t;
        if (fup && (!fdn || toggle == 0)) { t = ++hi; toggle = 1; }
        else                              { t = --lo; toggle = 0; }

        for (int i = tid; i < TS; i += 128) {
            tile[i] = sp[t * TS + i];
            tidx[i] = soi[t * TS + i];
        }
        __syncthreads();                 // sync 2: tile ready; zeroing ordered
        it++;
        for (int s = 0; s < TS / 32; s++) {
            float4 c = tile[s * 32 + lane];
            float dot0 = fmaf(qv0.z, c.z, fmaf(qv0.y, c.y, qv0.x * c.x));
            float dot1 = fmaf(qv1.z, c.z, fmaf(qv1.y, c.y, qv1.x * c.x));
            float d20 = fmaf(-2.f, dot0, qv0.w + c.w);
            float d21 = fmaf(-2.f, dot1, qv1.w + c.w);
            bool a0 = d20 < th0;
            bool a1 = d21 < th1;
            if (__ballot_sync(0xffffffffu, a0 | a1)) {
                if (bc0 > 16) { knn_flush(kd0, bc0, th0, lane); a0 = d20 < th0; }
                if (bc1 > 16) { knn_flush(kd1, bc1, th1, lane); a1 = d21 < th1; }
                unsigned m0 = __ballot_sync(0xffffffffu, a0);
                unsigned m1 = __ballot_sync(0xffffffffu, a1);
                int oi = tidx[s * 32 + lane];
                if (m0) {
                    int off = __popc(m0 & ((1u << lane) - 1u));
                    if (a0) kd0[16 + bc0 + off] = (((ull)senc(d20)) << 32) | (unsigned)oi;
                    bc0 += __popc(m0);
                }
                if (m1) {
                    int off = __popc(m1 & ((1u << lane) - 1u));
                    if (a1) kd1[16 + bc1 + off] = (((ull)senc(d21)) << 32) | (unsigned)oi;
                    bc1 += __popc(m1);
                }
            }
        }
    }
    if (bc0 > 0) knn_flush(kd0, bc0, th0, lane);
    if (bc1 > 0) knn_flush(kd1, bc1, th1, lane);
    if (lane < 16) {
        g_idx[((size_t)b * NN + oq0) * KK + lane] = (int)(unsigned)(kd0[lane] & 0xFFFFFFFFu);
        g_idx[((size_t)b * NN + oq1) * KK + lane] = (int)(unsigned)(kd1[lane] & 0xFFFFFFFFu);
    }
}

// ---------------------------------------------------------------------------
// Kernel 3: fused posenc + attn MLPs + softmax + combine + out projection.
// (R13/R9-exact scalar FFMA2 version; measured 165-166 us)
// ---------------------------------------------------------------------------
#define AQ 8
#define SQSTRIDE 640

__device__ __forceinline__ void mv16x64(const ull* __restrict__ Sq,
                                        const ulonglong2* __restrict__ w4, int l,
                                        ull aL[8], ull aH[8]) {
#pragma unroll
    for (int kp = 0; kp < 8; kp++) { aL[kp] = 0ull; aH[kp] = 0ull; }
#pragma unroll 4
    for (int jp = 0; jp < 32; jp++) {
        ulonglong2 wpp = w4[jp * 32 + l];
        {
            float wl, wh;
            upk(wpp.x, wl, wh);
            ull wl2 = pk(wl, wl), wh2 = pk(wh, wh);
            const ulonglong2* s = (const ulonglong2*)(Sq + (2 * jp) * 10);
#pragma unroll
            for (int kp2 = 0; kp2 < 4; kp2++) {
                ulonglong2 sv = s[kp2];
                aL[2 * kp2]     = f2fma(sv.x, wl2, aL[2 * kp2]);
                aH[2 * kp2]     = f2fma(sv.x, wh2, aH[2 * kp2]);
                aL[2 * kp2 + 1] = f2fma(sv.y, wl2, aL[2 * kp2 + 1]);
                aH[2 * kp2 + 1] = f2fma(sv.y, wh2, aH[2 * kp2 + 1]);
            }
        }
        {
            float wl, wh;
            upk(wpp.y, wl, wh);
            ull wl2 = pk(wl, wl), wh2 = pk(wh, wh);
            const ulonglong2* s = (const ulonglong2*)(Sq + (2 * jp + 1) * 10);
#pragma unroll
            for (int kp2 = 0; kp2 < 4; kp2++) {
                ulonglong2 sv = s[kp2];
                aL[2 * kp2]     = f2fma(sv.x, wl2, aL[2 * kp2]);
                aH[2 * kp2]     = f2fma(sv.x, wh2, aH[2 * kp2]);
                aL[2 * kp2 + 1] = f2fma(sv.y, wl2, aL[2 * kp2 + 1]);
                aH[2 * kp2 + 1] = f2fma(sv.y, wh2, aH[2 * kp2 + 1]);
            }
        }
    }
}

__global__ void __launch_bounds__(256) attn_kernel(
        const float* __restrict__ feat,
        const float* __restrict__ pe_w1, const float* __restrict__ pe_b1,
        const float* __restrict__ pe_w2, const float* __restrict__ pe_b2,
        const float* __restrict__ at_w1, const float* __restrict__ at_b1,
        const float* __restrict__ at_w2, const float* __restrict__ at_b2,
        const float* __restrict__ out_w, const float* __restrict__ out_b,
        float* __restrict__ out) {
    extern __shared__ ull smu[];
    ulonglong2* w4_pe2 = (ulonglong2*)smu;
    ulonglong2* w4_at1 = (ulonglong2*)(smu + 2048);
    ulonglong2* w4_at2 = (ulonglong2*)(smu + 4096);
    ull* Sp2    = smu + 6144;
    float* s_pe1 = (float*)(Sp2 + AQ * SQSTRIDE);
    float* s_b   = s_pe1 + 192;
    float* relb  = s_b + 320;
    float* resb  = relb + AQ * 64;
    int*   idxb  = (int*)(resb + AQ * 64);

    int tid = threadIdx.x;
    for (int e = tid; e < 1024; e += 256) {
        int jp = e >> 5, l2 = e & 31;
        int j0 = 2 * jp, j1 = 2 * jp + 1;
        w4_pe2[e] = make_ulonglong2(pk(pe_w2[j0 * 64 + l2], pe_w2[j0 * 64 + l2 + 32]),
                                    pk(pe_w2[j1 * 64 + l2], pe_w2[j1 * 64 + l2 + 32]));
        w4_at1[e] = make_ulonglong2(pk(at_w1[j0 * 64 + l2], at_w1[j0 * 64 + l2 + 32]),
                                    pk(at_w1[j1 * 64 + l2], at_w1[j1 * 64 + l2 + 32]));
        w4_at2[e] = make_ulonglong2(pk(at_w2[j0 * 64 + l2], at_w2[j0 * 64 + l2 + 32]),
                                    pk(at_w2[j1 * 64 + l2], at_w2[j1 * 64 + l2 + 32]));
    }
    if (tid < 192) s_pe1[tid] = pe_w1[tid];
    if (tid < 64) {
        s_b[tid]       = pe_b1[tid];
        s_b[64 + tid]  = pe_b2[tid];
        s_b[128 + tid] = at_b1[tid];
        s_b[192 + tid] = at_b2[tid];
        s_b[256 + tid] = out_b[tid];
    }

    int wid = tid >> 5;
    int l   = tid & 31;
    int g   = blockIdx.x * AQ + wid;
    int bbase = g & ~(NN - 1);

    float q_lo, q_hi;
    upk(g_q2[(size_t)g * 32 + l], q_lo, q_hi);

    if (l < KK) {
        int ii = g_idx[(size_t)g * KK + l];
        idxb[wid * KK + l] = ii;
        float4 np = g_pos4[bbase + ii];
        float4 qp = g_pos4[g];
        relb[(wid * KK + l) * 4 + 0] = np.x - qp.x;
        relb[(wid * KK + l) * 4 + 1] = np.y - qp.y;
        relb[(wid * KK + l) * 4 + 2] = np.z - qp.z;
    }
    __syncthreads();

    ull* Sq = Sp2 + wid * SQSTRIDE;

    // Stage A: pe1 = relu(rel @ pe_w1 + pe_b1)
    {
        float w0l = s_pe1[l],      w1l = s_pe1[64 + l],  w2l = s_pe1[128 + l];
        float w0h = s_pe1[l + 32], w1h = s_pe1[96 + l],  w2h = s_pe1[160 + l];
        float b1l = s_b[l], b1h = s_b[l + 32];
#pragma unroll
        for (int kp = 0; kp < 8; kp++) {
            const float* ra = relb + (wid * KK + 2 * kp) * 4;
            const float* rb = ra + 4;
            float pa = fmaxf(fmaf(ra[2], w2l, fmaf(ra[1], w1l, fmaf(ra[0], w0l, b1l))), 0.f);
            float pb = fmaxf(fmaf(rb[2], w2l, fmaf(rb[1], w1l, fmaf(rb[0], w0l, b1l))), 0.f);
            Sq[l * 10 + kp] = pk(pa, pb);
            float qa = fmaxf(fmaf(ra[2], w2h, fmaf(ra[1], w1h, fmaf(ra[0], w0h, b1h))), 0.f);
            float qb = fmaxf(fmaf(rb[2], w2h, fmaf(rb[1], w1h, fmaf(rb[0], w0h, b1h))), 0.f);
            Sq[(l + 32) * 10 + kp] = pk(qa, qb);
        }
    }
    __syncwarp();

    // Stage B: posenc = pe1 @ pe_w2 + pe_b2
    ull penL[8], penH[8];
    mv16x64(Sq, w4_pe2, l, penL, penH);
    {
        ull b2l = pk(s_b[64 + l], s_b[64 + l]);
        ull b2h = pk(s_b[64 + l + 32], s_b[64 + l + 32]);
#pragma unroll
        for (int kp = 0; kp < 8; kp++) {
            penL[kp] = f2add(penL[kp], b2l);
            penH[kp] = f2add(penH[kp], b2h);
        }
    }
    __syncwarp();

    // Stage C: h = q - k_feat + posenc
#pragma unroll
    for (int kp = 0; kp < 8; kp++) {
        int i0 = idxb[wid * KK + 2 * kp];
        int i1 = idxb[wid * KK + 2 * kp + 1];
        float k0l, k0h, k1l, k1h;
        upk(g_k2[(size_t)(bbase + i0) * 32 + l], k0l, k0h);
        upk(g_k2[(size_t)(bbase + i1) * 32 + l], k1l, k1h);
        float p0, p1;
        upk(penL[kp], p0, p1);
        Sq[l * 10 + kp] = pk(q_lo - k0l + p0, q_lo - k1l + p1);
        upk(penH[kp], p0, p1);
        Sq[(l + 32) * 10 + kp] = pk(q_hi - k0h + p0, q_hi - k1h + p1);
    }
    __syncwarp();

    // Stage D: a1 = relu(h @ at_w1 + at_b1)
    ull aL[8], aH[8];
    mv16x64(Sq, w4_at1, l, aL, aH);
    __syncwarp();
    {
        float bl = s_b[128 + l], bh = s_b[128 + l + 32];
#pragma unroll
        for (int kp = 0; kp < 8; kp++) {
            float x, y;
            upk(aL[kp], x, y);
            Sq[l * 10 + kp] = pk(fmaxf(x + bl, 0.f), fmaxf(y + bl, 0.f));
            upk(aH[kp], x, y);
            Sq[(l + 32) * 10 + kp] = pk(fmaxf(x + bh, 0.f), fmaxf(y + bh, 0.f));
        }
    }
    __syncwarp();

    // Stage E: logits = (a1 @ at_w2 + at_b2) / 8
    mv16x64(Sq, w4_at2, l, aL, aH);
    float el[KK], eh[KK];
    {
        float bl = s_b[192 + l], bh = s_b[192 + l + 32];
#pragma unroll
        for (int kp = 0; kp < 8; kp++) {
            float x, y;
            upk(aL[kp], x, y);
            el[2 * kp] = (x + bl) * 0.125f; el[2 * kp + 1] = (y + bl) * 0.125f;
            upk(aH[kp], x, y);
            eh[2 * kp] = (x + bh) * 0.125f; eh[2 * kp + 1] = (y + bh) * 0.125f;
        }
    }

    // softmax over K per channel + combine with (v + posenc)
    float ml = el[0], mh = eh[0];
#pragma unroll
    for (int k = 1; k < KK; k++) { ml = fmaxf(ml, el[k]); mh = fmaxf(mh, eh[k]); }
    float sl = 0.f, sh = 0.f;
#pragma unroll
    for (int k = 0; k < KK; k++) {
        el[k] = __expf(el[k] - ml); sl += el[k];
        eh[k] = __expf(eh[k] - mh); sh += eh[k];
    }
    float il = 1.f / sl, ih = 1.f / sh;
    float res_lo = 0.f, res_hi = 0.f;
#pragma unroll
    for (int kp = 0; kp < 8; kp++) {
        int i0 = idxb[wid * KK + 2 * kp];
        int i1 = idxb[wid * KK + 2 * kp + 1];
        float v0l, v0h, v1l, v1h;
        upk(g_v2[(size_t)(bbase + i0) * 32 + l], v0l, v0h);
        upk(g_v2[(size_t)(bbase + i1) * 32 + l], v1l, v1h);
        float p0, p1;
        upk(penL[kp], p0, p1);
        res_lo = fmaf(el[2 * kp] * il,     v0l + p0, res_lo);
        res_lo = fmaf(el[2 * kp + 1] * il, v1l + p1, res_lo);
        upk(penH[kp], p0, p1);
        res_hi = fmaf(eh[2 * kp] * ih,     v0h + p0, res_hi);
        res_hi = fmaf(eh[2 * kp + 1] * ih, v1h + p1, res_hi);
    }
    resb[wid * CC + l] = res_lo;
    resb[wid * CC + l + 32] = res_hi;
    __syncwarp();

    // final: out = res @ out_w + out_b + features (out_w via L1)
    {
        float ol = s_b[256 + l], oh = s_b[256 + l + 32];
#pragma unroll 4
        for (int j = 0; j < 64; j++) {
            float rj = resb[wid * CC + j];
            ol = fmaf(rj, __ldg(&out_w[j * 64 + l]), ol);
            oh = fmaf(rj, __ldg(&out_w[j * 64 + l + 32]), oh);
        }
        out[(size_t)g * CC + l]      = ol + feat[(size_t)g * CC + l];
        out[(size_t)g * CC + l + 32] = oh + feat[(size_t)g * CC + l + 32];
    }
}

// ---------------------------------------------------------------------------
extern "C" void kernel_launch(void* const* d_in, const int* in_sizes, int n_in,
                              void* d_out, int out_size) {
    const float* pos   = (const float*)d_in[0];
    const float* feat  = (const float*)d_in[1];
    const float* emb_w = (const float*)d_in[2];
    const float* emb_b = (const float*)d_in[3];
    const float* wq    = (const float*)d_in[4];
    const float* wk    = (const float*)d_in[5];
    const float* wv    = (const float*)d_in[6];
    const float* pe_w1 = (const float*)d_in[7];
    const float* pe_b1 = (const float*)d_in[8];
    const float* pe_w2 = (const float*)d_in[9];
    const float* pe_b2 = (const float*)d_in[10];
    const float* at_w1 = (const float*)d_in[11];
    const float* at_b1 = (const float*)d_in[12];
    const float* at_w2 = (const float*)d_in[13];
    const float* at_b2 = (const float*)d_in[14];
    const float* out_w = (const float*)d_in[15];
    const float* out_b = (const float*)d_in[16];
    float* out = (float*)d_out;

    int proj_smem = (8192 + PW * 576 + 32) * 8;
    int knn_smem  = (512 + 512 + 128 + 1) * 8;
    int attn_smem = (6144 + AQ * SQSTRIDE) * 8
                  + (192 + 320 + AQ * 64 * 2) * 4 + AQ * KK * 4;
    cudaFuncSetAttribute(proj_kernel, cudaFuncAttributeMaxDynamicSharedMemorySize, proj_smem);
    cudaFuncSetAttribute(knn_kernel, cudaFuncAttributeMaxDynamicSharedMemorySize, knn_smem);
    cudaFuncSetAttribute(attn_kernel, cudaFuncAttributeMaxDynamicSharedMemorySize, attn_smem);

    init_kernel<<<BB, NBINS>>>();
    prep_kernel<<<BN / 256, 256>>>(pos);
    hist_kernel<<<BN / 256, 256>>>();
    scan_kernel<<<BB, NBINS>>>();
    scatter_kernel<<<BN / 256, 256>>>();
    bounds_kernel<<<BB, 1024>>>();
    proj_kernel<<<BN / (PW * 16), 128, proj_smem>>>(feat, emb_w, emb_b, wq, wk, wv);
    knn_kernel<<<dim3(NN / QPB, BB), 128, knn_smem>>>();
    attn_kernel<<<BN / AQ, 256, attn_smem>>>(feat, pe_w1, pe_b1, pe_w2, pe_b2,
                                             at_w1, at_b1, at_w2, at_b2, out_w, out_b, out);
}

// round 17
// speedup vs baseline: 1.1652x; 1.0452x over previous
#include <cuda_runtime.h>
#include <math.h>
#include <float.h>

#define BB 2
#define NN 8192
#define KK 16
#define CC 64
#define BN (BB*NN)

typedef unsigned long long ull;

__device__ __forceinline__ ull pk(float a, float b) {
    ull d; asm("mov.b64 %0,{%1,%2};" : "=l"(d) : "f"(a), "f"(b)); return d;
}
__device__ __forceinline__ void upk(ull s, float& a, float& b) {
    asm("mov.b64 {%0,%1},%2;" : "=f"(a), "=f"(b) : "l"(s));
}
__device__ __forceinline__ ull f2fma(ull a, ull b, ull c) {
    ull d; asm("fma.rn.f32x2 %0,%1,%2,%3;" : "=l"(d) : "l"(a), "l"(b), "l"(c)); return d;
}
__device__ __forceinline__ ull f2add(ull a, ull b) {
    ull d; asm("add.rn.f32x2 %0,%1,%2;" : "=l"(d) : "l"(a), "l"(b)); return d;
}
__device__ __forceinline__ unsigned senc(float d) {
    unsigned u = __float_as_uint(d);
    unsigned mask = ((unsigned)(((int)u) >> 31)) | 0x80000000u;
    return u ^ mask;
}

// scratch (device globals — no runtime allocation; zero-initialized)
__device__ ull    g_q2[BN*32];
__device__ ull    g_k2[BN*32];
__device__ ull    g_v2[BN*32];
__device__ int    g_idx[BN*KK];
__device__ float4 g_pos4[BN];
__device__ float4 s_pos4g[BN];
__device__ int    s_oidxg[BN];

#define TS 256
#define NT (NN/TS)   // 32 tiles
#define QPB 8        // binned queries per knn block (4 warps)
#define NBINS 512

// fixed clamped binning range (correctness is binning-independent: selection
// is exact and prune bounds are computed from the actual scattered data)
#define RMINC 0.2f
#define RMAXC 4.0f
#define RINVC ((float)NBINS / (RMAXC - RMINC))

__device__ unsigned g_hist[BB][NBINS];   // self-cleaned by scatter_kernel
__device__ unsigned g_curs[BB][NBINS];
__device__ float    g_maxbelow[BB][NT + 1];
__device__ float    g_minabove[BB][NT + 1];

__device__ __forceinline__ int rbin(float r) {
    int bin = (int)((r - RMINC) * RINVC);
    return min(max(bin, 0), NBINS - 1);
}

// ---------------------------------------------------------------------------
// Kernel 0a: pos4 (exact fmaf chain) + histogram (fixed bins).
// ---------------------------------------------------------------------------
__global__ void prep_hist_kernel(const float* __restrict__ pos) {
    int i = blockIdx.x * 256 + threadIdx.x;
    int b = i / NN;
    float x = pos[3 * i], y = pos[3 * i + 1], z = pos[3 * i + 2];
    float w = fmaf(z, z, fmaf(y, y, x * x));
    g_pos4[i] = make_float4(x, y, z, w);
    atomicAdd(&g_hist[b][rbin(sqrtf(w))], 1u);
}

// Kernel 0b: exclusive prefix sum of hist -> cursors.
__global__ void scan_kernel() {
    __shared__ unsigned sh[NBINS];
    int b = blockIdx.x, tid = threadIdx.x;
    sh[tid] = g_hist[b][tid];
    __syncthreads();
    for (int off = 1; off < NBINS; off <<= 1) {
        unsigned v = (tid >= off) ? sh[tid - off] : 0u;
        __syncthreads();
        sh[tid] += v;
        __syncthreads();
    }
    g_curs[b][tid] = sh[tid] - g_hist[b][tid];
}

// Kernel 0c: scatter into bin order; zero hist for the next graph replay
// (hist already consumed by scan; scatter doesn't read it).
__global__ void scatter_kernel() {
    int i = blockIdx.x * 256 + threadIdx.x;
    int b = i / NN;
    float4 p = g_pos4[i];
    unsigned pos = atomicAdd(&g_curs[b][rbin(sqrtf(p.w))], 1u);
    s_pos4g[(size_t)b * NN + pos] = p;
    s_oidxg[(size_t)b * NN + pos] = i - b * NN;
    if (i < BB * NBINS) g_hist[i / NBINS][i % NBINS] = 0;
}

// Kernel 0d: exact per-tile radius min/max -> prefix max / suffix min.
__global__ void __launch_bounds__(1024) bounds_kernel() {
    __shared__ unsigned tmin[NT], tmax[NT];
    int b = blockIdx.x, tid = threadIdx.x;
    if (tid < NT) { tmin[tid] = 0xFFFFFFFFu; tmax[tid] = 0u; }
    __syncthreads();
    unsigned mn = 0xFFFFFFFFu, mx = 0u;
    int base = tid * 8;
    int t = base / TS;
#pragma unroll
    for (int e = 0; e < 8; e++) {
        unsigned wb = __float_as_uint(s_pos4g[(size_t)b * NN + base + e].w);
        mn = min(mn, wb);
        mx = max(mx, wb);
    }
    atomicMin(&tmin[t], mn);
    atomicMax(&tmax[t], mx);
    __syncthreads();
    if (tid == 0) {
        float runmax = 0.f;
        for (int k = 0; k <= NT; k++) {
            g_maxbelow[b][k] = (k == 0) ? 0.f : runmax;
            if (k < NT) runmax = fmaxf(runmax, sqrtf(__uint_as_float(tmax[k])));
        }
        float runmin = FLT_MAX;
        for (int k = NT; k >= 0; k--) {
            g_minabove[b][k] = runmin;
            if (k > 0) runmin = fminf(runmin, sqrtf(__uint_as_float(tmin[k - 1])));
        }
    }
}

// ---------------------------------------------------------------------------
// Kernel 1: x = feat@emb_w + emb_b ; q/k/v = x@wq/wk/wv.  (R13-exact)
// ---------------------------------------------------------------------------
#define PW 4
__global__ void __launch_bounds__(128) proj_kernel(
        const float* __restrict__ feat,
        const float* __restrict__ emb_w, const float* __restrict__ emb_b,
        const float* __restrict__ wq, const float* __restrict__ wk,
        const float* __restrict__ wv) {
    extern __shared__ ull pu[];
    ull* we2 = pu;
    ull* wq2 = pu + 2048;
    ull* wk2 = pu + 4096;
    ull* wv2 = pu + 6144;
    ull* Sbase = pu + 8192;
    ull* ebp = Sbase + PW * 576;

    int tid = threadIdx.x, lane = tid & 31, w = tid >> 5;
    for (int e = tid; e < 2048; e += 128) {
        int j = e >> 5, l2 = e & 31;
        we2[e] = pk(emb_w[j * 64 + l2], emb_w[j * 64 + l2 + 32]);
        wq2[e] = pk(wq[j * 64 + l2],   wq[j * 64 + l2 + 32]);
        wk2[e] = pk(wk[j * 64 + l2],   wk[j * 64 + l2 + 32]);
        wv2[e] = pk(wv[j * 64 + l2],   wv[j * 64 + l2 + 32]);
    }
    if (tid < 32) ebp[tid] = pk(emb_b[tid], emb_b[tid + 32]);

    int rows = (blockIdx.x * PW + w) * 16;
    ull* S = Sbase + w * 576;

#pragma unroll
    for (int rp = 0; rp < 8; rp++) {
        const float* f0 = feat + (size_t)(rows + 2 * rp) * 64;
        const float* f1 = f0 + 64;
        S[lane * 9 + rp]        = pk(f0[lane],      f1[lane]);
        S[(lane + 32) * 9 + rp] = pk(f0[lane + 32], f1[lane + 32]);
    }
    __syncthreads();

    ull xL[8], xH[8];
    {
        float bl, bh;
        upk(ebp[lane], bl, bh);
        ull bl2 = pk(bl, bl), bh2 = pk(bh, bh);
#pragma unroll
        for (int rp = 0; rp < 8; rp++) { xL[rp] = bl2; xH[rp] = bh2; }
    }
#pragma unroll 4
    for (int j = 0; j < 64; j++) {
        ull wp = we2[j * 32 + lane];
        float wl, wh;
        upk(wp, wl, wh);
        ull wl2 = pk(wl, wl), wh2 = pk(wh, wh);
        const ull* s = S + j * 9;
#pragma unroll
        for (int rp = 0; rp < 8; rp++) {
            ull s2 = s[rp];
            xL[rp] = f2fma(s2, wl2, xL[rp]);
            xH[rp] = f2fma(s2, wh2, xH[rp]);
        }
    }
    __syncwarp();
#pragma unroll
    for (int rp = 0; rp < 8; rp++) {
        S[lane * 9 + rp]        = xL[rp];
        S[(lane + 32) * 9 + rp] = xH[rp];
    }
    __syncwarp();

    ull qL[8], qH[8], kL[8], kH[8], vL[8], vH[8];
#pragma unroll
    for (int rp = 0; rp < 8; rp++) {
        qL[rp] = qH[rp] = kL[rp] = kH[rp] = vL[rp] = vH[rp] = 0ull;
    }
#pragma unroll 2
    for (int j = 0; j < 64; j++) {
        float a, b;
        upk(wq2[j * 32 + lane], a, b);
        ull wql = pk(a, a), wqh = pk(b, b);
        upk(wk2[j * 32 + lane], a, b);
        ull wkl = pk(a, a), wkh = pk(b, b);
        upk(wv2[j * 32 + lane], a, b);
        ull wvl = pk(a, a), wvh = pk(b, b);
        const ull* s = S + j * 9;
#pragma unroll
        for (int rp = 0; rp < 8; rp++) {
            ull s2 = s[rp];
            qL[rp] = f2fma(s2, wql, qL[rp]);
            qH[rp] = f2fma(s2, wqh, qH[rp]);
            kL[rp] = f2fma(s2, wkl, kL[rp]);
            kH[rp] = f2fma(s2, wkh, kH[rp]);
            vL[rp] = f2fma(s2, wvl, vL[rp]);
            vH[rp] = f2fma(s2, wvh, vH[rp]);
        }
    }

#pragma unroll
    for (int rp = 0; rp < 8; rp++) {
        size_t r0 = (size_t)(rows + 2 * rp) * 32 + lane;
        size_t r1 = r0 + 32;
        float a0, a1, b0, b1;
        upk(qL[rp], a0, a1); upk(qH[rp], b0, b1);
        g_q2[r0] = pk(a0, b0); g_q2[r1] = pk(a1, b1);
        upk(kL[rp], a0, a1); upk(kH[rp], b0, b1);
        g_k2[r0] = pk(a0, b0); g_k2[r1] = pk(a1, b1);
        upk(vL[rp], a0, a1); upk(vH[rp], b0, b1);
        g_v2[r0] = pk(a0, b0); g_v2[r1] = pk(a1, b1);
    }
}

// ---------------------------------------------------------------------------
// Kernel 2: KNN — R16-exact (QPB=8 block-tiled radius-band expansion,
// double-buffered flags, u64-key flush).
// ---------------------------------------------------------------------------
#define FSLOTS 64

__device__ __noinline__ void knn_flush(ull* kd, int& bc, float& theta, int lane) {
    int n = 16 + bc;
    ull k0 = (lane < n) ? kd[lane] : ~0ull;
    ull k1 = (lane + 32 < n) ? kd[lane + 32] : ~0ull;
    int r0 = 0, r1 = 0;
    for (int j = 0; j < n; j++) {
        ull kj = kd[j];
        r0 += (kj < k0);
        r1 += (kj < k1);
    }
    __syncwarp();
    if (r0 < 16) kd[r0] = k0;
    if (r1 < 16) kd[r1] = k1;
    __syncwarp();
    unsigned hi = (unsigned)(kd[15] >> 32);
    unsigned u = (hi & 0x80000000u) ? (hi ^ 0x80000000u) : ~hi;
    theta = __uint_as_float(u);
    bc = 0;
}

__global__ void __launch_bounds__(128) knn_kernel() {
    extern __shared__ ull ku[];
    float4* tile = (float4*)ku;
    ull*    kbuf = ku + 512;
    int*    tidx = (int*)(ku + 1024);
    int*    flg  = (int*)(ku + 1024 + 128);

    int tid = threadIdx.x, lane = tid & 31, w = tid >> 5;
    int b = blockIdx.y;
    int p0 = blockIdx.x * QPB + 2 * w;
    int p1 = p0 + 1;
    const float4* sp = s_pos4g + (size_t)b * NN;
    const int*   soi = s_oidxg + (size_t)b * NN;
    float4 qv0 = sp[p0], qv1 = sp[p1];
    float rq0 = sqrtf(qv0.w), rq1 = sqrtf(qv1.w);
    int oq0 = soi[p0], oq1 = soi[p1];

    ull* kd0 = kbuf + (w * 2 + 0) * FSLOTS;
    ull* kd1 = kbuf + (w * 2 + 1) * FSLOTS;
    if (lane < 16) {
        kd0[lane] = (((ull)0xFF7FFFFFu) << 32) | (unsigned)lane;
        kd1[lane] = (((ull)0xFF7FFFFFu) << 32) | (unsigned)lane;
    }
    if (tid < 4) flg[tid] = 0;
    __syncwarp();

    float th0 = FLT_MAX, th1 = FLT_MAX;
    int bc0 = 0, bc1 = 0;
    int h = (blockIdx.x * QPB) / TS;

    for (int i = tid; i < TS; i += 128) {
        tile[i] = sp[h * TS + i];
        tidx[i] = soi[h * TS + i];
    }
    __syncthreads();
    {
        float4 c = tile[lane];
        float dot0 = fmaf(qv0.z, c.z, fmaf(qv0.y, c.y, qv0.x * c.x));
        float dot1 = fmaf(qv1.z, c.z, fmaf(qv1.y, c.y, qv1.x * c.x));
        float d20 = fmaf(-2.f, dot0, qv0.w + c.w);
        float d21 = fmaf(-2.f, dot1, qv1.w + c.w);
        int oi = tidx[lane];
        kd0[16 + lane] = (((ull)senc(d20)) << 32) | (unsigned)oi;
        kd1[16 + lane] = (((ull)senc(d21)) << 32) | (unsigned)oi;
        __syncwarp();
        bc0 = 32; knn_flush(kd0, bc0, th0, lane);
        bc1 = 32; knn_flush(kd1, bc1, th1, lane);
    }
    for (int s = 1; s < TS / 32; s++) {
        float4 c = tile[s * 32 + lane];
        float dot0 = fmaf(qv0.z, c.z, fmaf(qv0.y, c.y, qv0.x * c.x));
        float dot1 = fmaf(qv1.z, c.z, fmaf(qv1.y, c.y, qv1.x * c.x));
        float d20 = fmaf(-2.f, dot0, qv0.w + c.w);
        float d21 = fmaf(-2.f, dot1, qv1.w + c.w);
        bool a0 = d20 < th0;
        bool a1 = d21 < th1;
        if (__ballot_sync(0xffffffffu, a0 | a1)) {
            if (bc0 > 16) { knn_flush(kd0, bc0, th0, lane); a0 = d20 < th0; }
            if (bc1 > 16) { knn_flush(kd1, bc1, th1, lane); a1 = d21 < th1; }
            unsigned m0 = __ballot_sync(0xffffffffu, a0);
            unsigned m1 = __ballot_sync(0xffffffffu, a1);
            int oi = tidx[s * 32 + lane];
            if (m0) {
                int off = __popc(m0 & ((1u << lane) - 1u));
                if (a0) kd0[16 + bc0 + off] = (((ull)senc(d20)) << 32) | (unsigned)oi;
                bc0 += __popc(m0);
            }
            if (m1) {
                int off = __popc(m1 & ((1u << lane) - 1u));
                if (a1) kd1[16 + bc1 + off] = (((ull)senc(d21)) << 32) | (unsigned)oi;
                bc1 += __popc(m1);
            }
        }
    }

    int lo = h, hi = h, toggle = 0, it = 0;
    while (true) {
        int cur = (it & 1) * 2;
        bool ndn = false, nup = false;
        if (lo > 0) {
            float rb = g_maxbelow[b][lo];
            float g0 = rq0 - rb, g1 = rq1 - rb;
            if (!(g0 > 0.f && g0 * g0 >= th0 * 1.0001f)) ndn = true;
            if (!(g1 > 0.f && g1 * g1 >= th1 * 1.0001f)) ndn = true;
        }
        if (hi < NT - 1) {
            float ra = g_minabove[b][hi + 1];
            float g0 = ra - rq0, g1 = ra - rq1;
            if (!(g0 > 0.f && g0 * g0 >= th0 * 1.0001f)) nup = true;
            if (!(g1 > 0.f && g1 * g1 >= th1 * 1.0001f)) nup = true;
        }
        if (lane == 0) {
            if (ndn) atomicOr(&flg[cur + 0], 1);
            if (nup) atomicOr(&flg[cur + 1], 1);
        }
        __syncthreads();
        int fdn = flg[cur + 0], fup = flg[cur + 1];
        if (tid < 2) flg[(cur ^ 2) + tid] = 0;
        if (!fdn && !fup) break;
        int t;
        if (fup && (!fdn || toggle == 0)) { t = ++hi; toggle = 1; }
        else                              { t = --lo; toggle = 0; }

        for (int i = tid; i < TS; i += 128) {
            tile[i] = sp[t * TS + i];
            tidx[i] = soi[t * TS + i];
        }
        __syncthreads();
        it++;
        for (int s = 0; s < TS / 32; s++) {
            float4 c = tile[s * 32 + lane];
            float dot0 = fmaf(qv0.z, c.z, fmaf(qv0.y, c.y, qv0.x * c.x));
            float dot1 = fmaf(qv1.z, c.z, fmaf(qv1.y, c.y, qv1.x * c.x));
            float d20 = fmaf(-2.f, dot0, qv0.w + c.w);
            float d21 = fmaf(-2.f, dot1, qv1.w + c.w);
            bool a0 = d20 < th0;
            bool a1 = d21 < th1;
            if (__ballot_sync(0xffffffffu, a0 | a1)) {
                if (bc0 > 16) { knn_flush(kd0, bc0, th0, lane); a0 = d20 < th0; }
                if (bc1 > 16) { knn_flush(kd1, bc1, th1, lane); a1 = d21 < th1; }
                unsigned m0 = __ballot_sync(0xffffffffu, a0);
                unsigned m1 = __ballot_sync(0xffffffffu, a1);
                int oi = tidx[s * 32 + lane];
                if (m0) {
                    int off = __popc(m0 & ((1u << lane) - 1u));
                    if (a0) kd0[16 + bc0 + off] = (((ull)senc(d20)) << 32) | (unsigned)oi;
                    bc0 += __popc(m0);
                }
                if (m1) {
                    int off = __popc(m1 & ((1u << lane) - 1u));
                    if (a1) kd1[16 + bc1 + off] = (((ull)senc(d21)) << 32) | (unsigned)oi;
                    bc1 += __popc(m1);
                }
            }
        }
    }
    if (bc0 > 0) knn_flush(kd0, bc0, th0, lane);
    if (bc1 > 0) knn_flush(kd1, bc1, th1, lane);
    if (lane < 16) {
        g_idx[((size_t)b * NN + oq0) * KK + lane] = (int)(unsigned)(kd0[lane] & 0xFFFFFFFFu);
        g_idx[((size_t)b * NN + oq1) * KK + lane] = (int)(unsigned)(kd1[lane] & 0xFFFFFFFFu);
    }
}

// ---------------------------------------------------------------------------
// Kernel 3: fused posenc + attn MLPs + softmax + combine + out projection.
// (R13/R9-exact scalar FFMA2 version; measured 165-166 us)
// ---------------------------------------------------------------------------
#define AQ 8
#define SQSTRIDE 640

__device__ __forceinline__ void mv16x64(const ull* __restrict__ Sq,
                                        const ulonglong2* __restrict__ w4, int l,
                                        ull aL[8], ull aH[8]) {
#pragma unroll
    for (int kp = 0; kp < 8; kp++) { aL[kp] = 0ull; aH[kp] = 0ull; }
#pragma unroll 4
    for (int jp = 0; jp < 32; jp++) {
        ulonglong2 wpp = w4[jp * 32 + l];
        {
            float wl, wh;
            upk(wpp.x, wl, wh);
            ull wl2 = pk(wl, wl), wh2 = pk(wh, wh);
            const ulonglong2* s = (const ulonglong2*)(Sq + (2 * jp) * 10);
#pragma unroll
            for (int kp2 = 0; kp2 < 4; kp2++) {
                ulonglong2 sv = s[kp2];
                aL[2 * kp2]     = f2fma(sv.x, wl2, aL[2 * kp2]);
                aH[2 * kp2]     = f2fma(sv.x, wh2, aH[2 * kp2]);
                aL[2 * kp2 + 1] = f2fma(sv.y, wl2, aL[2 * kp2 + 1]);
                aH[2 * kp2 + 1] = f2fma(sv.y, wh2, aH[2 * kp2 + 1]);
            }
        }
        {
            float wl, wh;
            upk(wpp.y, wl, wh);
            ull wl2 = pk(wl, wl), wh2 = pk(wh, wh);
            const ulonglong2* s = (const ulonglong2*)(Sq + (2 * jp + 1) * 10);
#pragma unroll
            for (int kp2 = 0; kp2 < 4; kp2++) {
                ulonglong2 sv = s[kp2];
                aL[2 * kp2]     = f2fma(sv.x, wl2, aL[2 * kp2]);
                aH[2 * kp2]     = f2fma(sv.x, wh2, aH[2 * kp2]);
                aL[2 * kp2 + 1] = f2fma(sv.y, wl2, aL[2 * kp2 + 1]);
                aH[2 * kp2 + 1] = f2fma(sv.y, wh2, aH[2 * kp2 + 1]);
            }
        }
    }
}

__global__ void __launch_bounds__(256) attn_kernel(
        const float* __restrict__ feat,
        const float* __restrict__ pe_w1, const float* __restrict__ pe_b1,
        const float* __restrict__ pe_w2, const float* __restrict__ pe_b2,
        const float* __restrict__ at_w1, const float* __restrict__ at_b1,
        const float* __restrict__ at_w2, const float* __restrict__ at_b2,
        const float* __restrict__ out_w, const float* __restrict__ out_b,
        float* __restrict__ out) {
    extern __shared__ ull smu[];
    ulonglong2* w4_pe2 = (ulonglong2*)smu;
    ulonglong2* w4_at1 = (ulonglong2*)(smu + 2048);
    ulonglong2* w4_at2 = (ulonglong2*)(smu + 4096);
    ull* Sp2    = smu + 6144;
    float* s_pe1 = (float*)(Sp2 + AQ * SQSTRIDE);
    float* s_b   = s_pe1 + 192;
    float* relb  = s_b + 320;
    float* resb  = relb + AQ * 64;
    int*   idxb  = (int*)(resb + AQ * 64);

    int tid = threadIdx.x;
    for (int e = tid; e < 1024; e += 256) {
        int jp = e >> 5, l2 = e & 31;
        int j0 = 2 * jp, j1 = 2 * jp + 1;
        w4_pe2[e] = make_ulonglong2(pk(pe_w2[j0 * 64 + l2], pe_w2[j0 * 64 + l2 + 32]),
                                    pk(pe_w2[j1 * 64 + l2], pe_w2[j1 * 64 + l2 + 32]));
        w4_at1[e] = make_ulonglong2(pk(at_w1[j0 * 64 + l2], at_w1[j0 * 64 + l2 + 32]),
                                    pk(at_w1[j1 * 64 + l2], at_w1[j1 * 64 + l2 + 32]));
        w4_at2[e] = make_ulonglong2(pk(at_w2[j0 * 64 + l2], at_w2[j0 * 64 + l2 + 32]),
                                    pk(at_w2[j1 * 64 + l2], at_w2[j1 * 64 + l2 + 32]));
    }
    if (tid < 192) s_pe1[tid] = pe_w1[tid];
    if (tid < 64) {
        s_b[tid]       = pe_b1[tid];
        s_b[64 + tid]  = pe_b2[tid];
        s_b[128 + tid] = at_b1[tid];
        s_b[192 + tid] = at_b2[tid];
        s_b[256 + tid] = out_b[tid];
    }

    int wid = tid >> 5;
    int l   = tid & 31;
    int g   = blockIdx.x * AQ + wid;
    int bbase = g & ~(NN - 1);

    float q_lo, q_hi;
    upk(g_q2[(size_t)g * 32 + l], q_lo, q_hi);

    if (l < KK) {
        int ii = g_idx[(size_t)g * KK + l];
        idxb[wid * KK + l] = ii;
        float4 np = g_pos4[bbase + ii];
        float4 qp = g_pos4[g];
        relb[(wid * KK + l) * 4 + 0] = np.x - qp.x;
        relb[(wid * KK + l) * 4 + 1] = np.y - qp.y;
        relb[(wid * KK + l) * 4 + 2] = np.z - qp.z;
    }
    __syncthreads();

    ull* Sq = Sp2 + wid * SQSTRIDE;

    // Stage A: pe1 = relu(rel @ pe_w1 + pe_b1)
    {
        float w0l = s_pe1[l],      w1l = s_pe1[64 + l],  w2l = s_pe1[128 + l];
        float w0h = s_pe1[l + 32], w1h = s_pe1[96 + l],  w2h = s_pe1[160 + l];
        float b1l = s_b[l], b1h = s_b[l + 32];
#pragma unroll
        for (int kp = 0; kp < 8; kp++) {
            const float* ra = relb + (wid * KK + 2 * kp) * 4;
            const float* rb = ra + 4;
            float pa = fmaxf(fmaf(ra[2], w2l, fmaf(ra[1], w1l, fmaf(ra[0], w0l, b1l))), 0.f);
            float pb = fmaxf(fmaf(rb[2], w2l, fmaf(rb[1], w1l, fmaf(rb[0], w0l, b1l))), 0.f);
            Sq[l * 10 + kp] = pk(pa, pb);
            float qa = fmaxf(fmaf(ra[2], w2h, fmaf(ra[1], w1h, fmaf(ra[0], w0h, b1h))), 0.f);
            float qb = fmaxf(fmaf(rb[2], w2h, fmaf(rb[1], w1h, fmaf(rb[0], w0h, b1h))), 0.f);
            Sq[(l + 32) * 10 + kp] = pk(qa, qb);
        }
    }
    __syncwarp();

    // Stage B: posenc = pe1 @ pe_w2 + pe_b2
    ull penL[8], penH[8];
    mv16x64(Sq, w4_pe2, l, penL, penH);
    {
        ull b2l = pk(s_b[64 + l], s_b[64 + l]);
        ull b2h = pk(s_b[64 + l + 32], s_b[64 + l + 32]);
#pragma unroll
        for (int kp = 0; kp < 8; kp++) {
            penL[kp] = f2add(penL[kp], b2l);
            penH[kp] = f2add(penH[kp], b2h);
        }
    }
    __syncwarp();

    // Stage C: h = q - k_feat + posenc
#pragma unroll
    for (int kp = 0; kp < 8; kp++) {
        int i0 = idxb[wid * KK + 2 * kp];
        int i1 = idxb[wid * KK + 2 * kp + 1];
        float k0l, k0h, k1l, k1h;
        upk(g_k2[(size_t)(bbase + i0) * 32 + l], k0l, k0h);
        upk(g_k2[(size_t)(bbase + i1) * 32 + l], k1l, k1h);
        float p0, p1;
        upk(penL[kp], p0, p1);
        Sq[l * 10 + kp] = pk(q_lo - k0l + p0, q_lo - k1l + p1);
        upk(penH[kp], p0, p1);
        Sq[(l + 32) * 10 + kp] = pk(q_hi - k0h + p0, q_hi - k1h + p1);
    }
    __syncwarp();

    // Stage D: a1 = relu(h @ at_w1 + at_b1)
    ull aL[8], aH[8];
    mv16x64(Sq, w4_at1, l, aL, aH);
    __syncwarp();
    {
        float bl = s_b[128 + l], bh = s_b[128 + l + 32];
#pragma unroll
        for (int kp = 0; kp < 8; kp++) {
            float x, y;
            upk(aL[kp], x, y);
            Sq[l * 10 + kp] = pk(fmaxf(x + bl, 0.f), fmaxf(y + bl, 0.f));
            upk(aH[kp], x, y);
            Sq[(l + 32) * 10 + kp] = pk(fmaxf(x + bh, 0.f), fmaxf(y + bh, 0.f));
        }
    }
    __syncwarp();

    // Stage E: logits = (a1 @ at_w2 + at_b2) / 8
    mv16x64(Sq, w4_at2, l, aL, aH);
    float el[KK], eh[KK];
    {
        float bl = s_b[192 + l], bh = s_b[192 + l + 32];
#pragma unroll
        for (int kp = 0; kp < 8; kp++) {
            float x, y;
            upk(aL[kp], x, y);
            el[2 * kp] = (x + bl) * 0.125f; el[2 * kp + 1] = (y + bl) * 0.125f;
            upk(aH[kp], x, y);
            eh[2 * kp] = (x + bh) * 0.125f; eh[2 * kp + 1] = (y + bh) * 0.125f;
        }
    }

    // softmax over K per channel + combine with (v + posenc)
    float ml = el[0], mh = eh[0];
#pragma unroll
    for (int k = 1; k < KK; k++) { ml = fmaxf(ml, el[k]); mh = fmaxf(mh, eh[k]); }
    float sl = 0.f, sh = 0.f;
#pragma unroll
    for (int k = 0; k < KK; k++) {
        el[k] = __expf(el[k] - ml); sl += el[k];
        eh[k] = __expf(eh[k] - mh); sh += eh[k];
    }
    float il = 1.f / sl, ih = 1.f / sh;
    float res_lo = 0.f, res_hi = 0.f;
#pragma unroll
    for (int kp = 0; kp < 8; kp++) {
        int i0 = idxb[wid * KK + 2 * kp];
        int i1 = idxb[wid * KK + 2 * kp + 1];
        float v0l, v0h, v1l, v1h;
        upk(g_v2[(size_t)(bbase + i0) * 32 + l], v0l, v0h);
        upk(g_v2[(size_t)(bbase + i1) * 32 + l], v1l, v1h);
        float p0, p1;
        upk(penL[kp], p0, p1);
        res_lo = fmaf(el[2 * kp] * il,     v0l + p0, res_lo);
        res_lo = fmaf(el[2 * kp + 1] * il, v1l + p1, res_lo);
        upk(penH[kp], p0, p1);
        res_hi = fmaf(eh[2 * kp] * ih,     v0h + p0, res_hi);
        res_hi = fmaf(eh[2 * kp + 1] * ih, v1h + p1, res_hi);
    }
    resb[wid * CC + l] = res_lo;
    resb[wid * CC + l + 32] = res_hi;
    __syncwarp();

    // final: out = res @ out_w + out_b + features (out_w via L1)
    {
        float ol = s_b[256 + l], oh = s_b[256 + l + 32];
#pragma unroll 4
        for (int j = 0; j < 64; j++) {
            float rj = resb[wid * CC + j];
            ol = fmaf(rj, __ldg(&out_w[j * 64 + l]), ol);
            oh = fmaf(rj, __ldg(&out_w[j * 64 + l + 32]), oh);
        }
        out[(size_t)g * CC + l]      = ol + feat[(size_t)g * CC + l];
        out[(size_t)g * CC + l + 32] = oh + feat[(size_t)g * CC + l + 32];
    }
}

// ---------------------------------------------------------------------------
// aux stream/events, created once on the first (eager, non-captured) call;
// the captured graph contains only kernel launches and event edges.
// ---------------------------------------------------------------------------
struct AuxRes {
    cudaStream_t s;
    cudaEvent_t e0, e1;
    AuxRes() {
        cudaStreamCreate(&s);
        cudaEventCreateWithFlags(&e0, cudaEventDisableTiming);
        cudaEventCreateWithFlags(&e1, cudaEventDisableTiming);
    }
};
static AuxRes& aux() { static AuxRes a; return a; }

extern "C" void kernel_launch(void* const* d_in, const int* in_sizes, int n_in,
                              void* d_out, int out_size) {
    const float* pos   = (const float*)d_in[0];
    const float* feat  = (const float*)d_in[1];
    const float* emb_w = (const float*)d_in[2];
    const float* emb_b = (const float*)d_in[3];
    const float* wq    = (const float*)d_in[4];
    const float* wk    = (const float*)d_in[5];
    const float* wv    = (const float*)d_in[6];
    const float* pe_w1 = (const float*)d_in[7];
    const float* pe_b1 = (const float*)d_in[8];
    const float* pe_w2 = (const float*)d_in[9];
    const float* pe_b2 = (const float*)d_in[10];
    const float* at_w1 = (const float*)d_in[11];
    const float* at_b1 = (const float*)d_in[12];
    const float* at_w2 = (const float*)d_in[13];
    const float* at_b2 = (const float*)d_in[14];
    const float* out_w = (const float*)d_in[15];
    const float* out_b = (const float*)d_in[16];
    float* out = (float*)d_out;

    AuxRes& a = aux();

    int proj_smem = (8192 + PW * 576 + 32) * 8;
    int knn_smem  = (512 + 512 + 128 + 1) * 8;
    int attn_smem = (6144 + AQ * SQSTRIDE) * 8
                  + (192 + 320 + AQ * 64 * 2) * 4 + AQ * KK * 4;
    cudaFuncSetAttribute(proj_kernel, cudaFuncAttributeMaxDynamicSharedMemorySize, proj_smem);
    cudaFuncSetAttribute(knn_kernel, cudaFuncAttributeMaxDynamicSharedMemorySize, knn_smem);
    cudaFuncSetAttribute(attn_kernel, cudaFuncAttributeMaxDynamicSharedMemorySize, attn_smem);

    // fork: proj runs on the aux stream, overlapped with the knn chain
    cudaEventRecord(a.e0, 0);
    cudaStreamWaitEvent(a.s, a.e0, 0);
    proj_kernel<<<BN / (PW * 16), 128, proj_smem, a.s>>>(feat, emb_w, emb_b, wq, wk, wv);
    cudaEventRecord(a.e1, a.s);

    // knn chain on the main stream
    prep_hist_kernel<<<BN / 256, 256>>>(pos);
    scan_kernel<<<BB, NBINS>>>();
    scatter_kernel<<<BN / 256, 256>>>();
    bounds_kernel<<<BB, 1024>>>();
    knn_kernel<<<dim3(NN / QPB, BB), 128, knn_smem>>>();

    // join, then attn (depends on proj outputs + knn indices)
    cudaStreamWaitEvent(0, a.e1, 0);
    attn_kernel<<<BN / AQ, 256, attn_smem>>>(feat, pe_w1, pe_b1, pe_w2, pe_b2,
                                             at_w1, at_b1, at_w2, at_b2, out_w, out_b, out);
}